// round 14
// baseline (speedup 1.0000x reference)
#include <cuda_runtime.h>
#include <cuda_fp16.h>
#include <math.h>
#include <stdint.h>

#define T_LEN  2048
#define BSZ    2
#define E_DIM  1024
#define H_NUM  16
#define D_DIM  64
#define PLEN   32
#define BH     32
#define SCH    32               // state chunk
#define NSC    (T_LEN/SCH)      // 64
#define SCALING 0.125f
#define BETA    0.6931471805599453f

#define MROWS  (T_LEN*BSZ)      // 4096
#define NE     (E_DIM*E_DIM)

// ------------------------- scratch -----------------------------------------
__device__ float g_pq   [BH*PLEN*D_DIM];
__device__ float g_q    [BH*T_LEN*D_DIM];
__device__ float g_kp   [BH*T_LEN*D_DIM];
__device__ float g_kv   [BH*T_LEN*D_DIM];
__device__ float g_pattn[BH*T_LEN*PLEN];
__device__ float g_S    [BH*NSC*D_DIM*PLEN];

__device__ __half g_Ah  [MROWS*E_DIM];
__device__ __half g_PQh [64*E_DIM];
__device__ __half g_W4h [4*NE];          // Wq, Wpc, Wc, Wpq
__device__ __half g_WOh [NE];
__device__ __half g_ATh [MROWS*E_DIM];

// ------------------------- helpers -----------------------------------------
__device__ __forceinline__ uint32_t smem_u32(const void* p) {
    uint32_t a;
    asm("{ .reg .u64 t; cvta.to.shared.u64 t, %1; cvt.u32.u64 %0, t; }"
        : "=r"(a) : "l"(p));
    return a;
}
__device__ __forceinline__ uint32_t sw128(uint32_t off) {
    return off ^ ((off >> 3) & 0x70);
}
__device__ __forceinline__ void ldsm_x4(uint32_t* r, uint32_t addr) {
    asm volatile("ldmatrix.sync.aligned.m8n8.x4.shared.b16 {%0,%1,%2,%3}, [%4];"
                 : "=r"(r[0]), "=r"(r[1]), "=r"(r[2]), "=r"(r[3]) : "r"(addr));
}
__device__ __forceinline__ void mma16816(float* c, const uint32_t* a, const uint32_t* b) {
    asm volatile("mma.sync.aligned.m16n8k16.row.col.f32.f16.f16.f32 "
                 "{%0,%1,%2,%3}, {%4,%5,%6,%7}, {%8,%9}, {%0,%1,%2,%3};"
                 : "+f"(c[0]), "+f"(c[1]), "+f"(c[2]), "+f"(c[3])
                 : "r"(a[0]), "r"(a[1]), "r"(a[2]), "r"(a[3]), "r"(b[0]), "r"(b[1]));
}
__device__ __forceinline__ void cp16(uint32_t dst, const void* src, int sz) {
    asm volatile("cp.async.cg.shared.global [%0], [%1], 16, %2;"
                 :: "r"(dst), "l"(src), "r"(sz));
}
__device__ __forceinline__ void cp_commit() {
    asm volatile("cp.async.commit_group;" ::: "memory");
}
__device__ __forceinline__ void cp_wait1() {
    asm volatile("cp.async.wait_group 1;" ::: "memory");
}
__device__ __forceinline__ void cp_wait0() {
    asm volatile("cp.async.wait_group 0;" ::: "memory");
}

// ------------------------- dummy (shifts profiled slot) --------------------
__global__ void dummy_k() {}

// ------------------------- merged fp32 -> fp16 converter -------------------
#define NCVT 7
struct CvtArgs {
    const float4* s[NCVT];
    __half2*      h[NCVT];
    int           end[NCVT];
};

__global__ __launch_bounds__(256)
void cvt_all(CvtArgs A)
{
    int gi = blockIdx.x * 256 + threadIdx.x;
    int seg = 0;
    while (seg < NCVT && gi >= A.end[seg]) seg++;
    if (seg >= NCVT) return;
    int i = gi - (seg ? A.end[seg - 1] : 0);

    float4 v = A.s[seg][i];
    A.h[seg][2 * i]     = __half2(__float2half_rn(v.x), __float2half_rn(v.y));
    A.h[seg][2 * i + 1] = __half2(__float2half_rn(v.z), __float2half_rn(v.w));
}

// ------------------------- pipelined fp16 GEMM (R10 form) -------------------
__device__ __forceinline__ void g_load_stage(
    uint32_t sb, int slot,
    const __half* Ah, const __half* Bh,
    int bm, int bn, int kb, int M, int tid)
{
    const uint32_t abase = sb + slot * 32768;
    const uint32_t bbase = abase + 16384;
    const int c  = tid & 7;
    const int r0 = tid >> 3;
    const int kc = kb + c * 8;
#pragma unroll
    for (int ii = 0; ii < 4; ii++) {
        int r = r0 + ii * 32;
        uint32_t so = sw128((uint32_t)(r * 128 + c * 16));
        int m = bm + r;
        int mc = (m < M) ? m : (M - 1);
        cp16(abase + so, Ah + (size_t)mc * E_DIM + kc, (m < M) ? 16 : 0);
        cp16(bbase + so, Bh + (size_t)(bn + r) * E_DIM + kc, 16);
    }
}

__global__ __launch_bounds__(256, 2)
void gemm_mma(const __half* __restrict__ A0, const __half* __restrict__ A3,
              const __half* __restrict__ W,
              const float* b0, const float* b1, const float* b2, const float* b3,
              float* o0, float* o1, float* o2, float* o3,
              float s0, float s1, float s2, float s3,
              int M0, int M3, int mode, int Trows0, int Trows3)
{
    extern __shared__ char smem[];
    const uint32_t sb = smem_u32(smem);

    const int tid = threadIdx.x, wid = tid >> 5, lane = tid & 31;
    const int bm = blockIdx.y * 128, bn = blockIdx.x * 128;
    const int z = blockIdx.z;
    const int M     = (z == 3) ? M3 : M0;
    const int Trows = (z == 3) ? Trows3 : Trows0;
    if (bm >= M) return;
    const __half* Ah = (z == 3) ? A3 : A0;
    const __half* wh = W + (size_t)z * NE;
    const float* bias = (z == 0) ? b0 : ((z == 1) ? b1 : ((z == 2) ? b2 : b3));
    float* out        = (z == 0) ? o0 : ((z == 1) ? o1 : ((z == 2) ? o2 : o3));
    const float scale = (z == 0) ? s0 : ((z == 1) ? s1 : ((z == 2) ? s2 : s3));

    const int warpM = (wid >> 2) * 64;
    const int warpN = (wid & 3) * 32;
    const int li = lane >> 3, lr = lane & 7;

    float acc[4][4][4];
#pragma unroll
    for (int i = 0; i < 4; i++)
#pragma unroll
        for (int j = 0; j < 4; j++)
#pragma unroll
            for (int k = 0; k < 4; k++) acc[i][j][k] = 0.f;

    const int NK = E_DIM / 64;
    g_load_stage(sb, 0, Ah, wh, bm, bn, 0, M, tid);
    cp_commit();
    g_load_stage(sb, 1, Ah, wh, bm, bn, 64, M, tid);
    cp_commit();

    int slot = 0, next = 2;
    for (int ks = 0; ks < NK; ks++) {
        if (ks + 1 < NK) cp_wait1(); else cp_wait0();
        __syncthreads();
        if (ks + 2 < NK) {
            g_load_stage(sb, next, Ah, wh, bm, bn, (ks + 2) * 64, M, tid);
            cp_commit();
            if (++next == 3) next = 0;
        }

        const uint32_t abase = sb + slot * 32768;
        const uint32_t bbase = abase + 16384;
        if (++slot == 3) slot = 0;
#pragma unroll
        for (int kk = 0; kk < 4; kk++) {
            uint32_t bfr[2][4];
            const uint32_t kb2 = (uint32_t)(kk * 32 + (li & 1) * 16);
#pragma unroll
            for (int jn = 0; jn < 2; jn++) {
                uint32_t off = (uint32_t)((warpN + jn * 16 + (li >> 1) * 8 + lr) * 128) + kb2;
                ldsm_x4(bfr[jn], bbase + sw128(off));
            }
            const uint32_t ka = (uint32_t)(kk * 32 + (li >> 1) * 16);
#pragma unroll
            for (int i = 0; i < 4; i++) {
                uint32_t ah[4];
                uint32_t off = (uint32_t)((warpM + i * 16 + (li & 1) * 8 + lr) * 128) + ka;
                ldsm_x4(ah, abase + sw128(off));
#pragma unroll
                for (int j = 0; j < 4; j++)
                    mma16816(acc[i][j], ah, &bfr[j >> 1][(j & 1) * 2]);
            }
        }
    }

    const int g = lane >> 2, tg = lane & 3;
#pragma unroll
    for (int i = 0; i < 4; i++) {
#pragma unroll
        for (int j = 0; j < 4; j++) {
            int n0 = bn + warpN + j * 8 + tg * 2;
            float bx = bias[n0], by = bias[n0 + 1];
#pragma unroll
            for (int half = 0; half < 2; half++) {
                int m = bm + warpM + i * 16 + g + half * 8;
                if (m >= M) continue;
                float2 v;
                v.x = (acc[i][j][half * 2 + 0] + bx) * scale;
                v.y = (acc[i][j][half * 2 + 1] + by) * scale;
                if (mode == 0) {
                    *(float2*)&out[(size_t)m * E_DIM + n0] = v;
                } else {
                    int t = m >> 1, b = m & 1;
                    int h = n0 >> 6, d = n0 & 63;
                    *(float2*)&out[(size_t)((b * 16 + h) * Trows + t) * 64 + d] = v;
                }
            }
        }
    }
}

// ------------- merged pattn (softplus) + TWO 32-row local states ------------
// float4-vectorized LDS; strides: 68 (kps/pqs), 64 (kvs), 32 (ps).
__global__ __launch_bounds__(256, 2)
void pattn_local()
{
    const int bx = blockIdx.x, bh = blockIdx.y;
    extern __shared__ float sm[];
    float* kps = sm;                   // 64 x 68
    float* pqs = kps + 64 * 68;        // 32 x 68
    float* kvs = pqs + 32 * 68;        // 64 x 64
    float* ps  = kvs + 64 * 64;        // 64 x 32
    const size_t base = (size_t)bh * T_LEN + bx * 64;
    const int tid = threadIdx.x;

    for (int i = tid; i < 64 * 64; i += 256) {
        int s = i >> 6, d = i & 63;
        kps[s * 68 + d] = g_kp[(base + s) * 64 + d];
        kvs[i] = g_kv[(base + s) * 64 + d];
    }
    for (int i = tid; i < PLEN * 64; i += 256) {
        int p = i >> 6, d = i & 63;
        pqs[p * 68 + d] = g_pq[(size_t)bh * PLEN * D_DIM + i];
    }
    __syncthreads();

    {
        const int t  = tid >> 2;
        const int p0 = (tid & 3) * 8;
        const float4* kr = (const float4*)&kps[t * 68];
        float4 k4[16];
#pragma unroll
        for (int k = 0; k < 16; k++) k4[k] = kr[k];
#pragma unroll
        for (int pp = 0; pp < 8; pp++) {
            const float4* pq = (const float4*)&pqs[(p0 + pp) * 68];
            float a0 = 0.f, a1 = 0.f, a2 = 0.f, a3 = 0.f;
#pragma unroll
            for (int k = 0; k < 16; k++) {
                float4 p4 = pq[k];
                a0 += k4[k].x * p4.x;
                a1 += k4[k].y * p4.y;
                a2 += k4[k].z * p4.z;
                a3 += k4[k].w * p4.w;
            }
            float accv = (a0 + a1) + (a2 + a3);
            float zz = BETA * accv;
            float sp = (fmaxf(zz, 0.f) + log1pf(expf(-fabsf(zz)))) * (1.0f / BETA);
            ps[t * 32 + p0 + pp] = sp;
            g_pattn[(base + t) * PLEN + p0 + pp] = sp;
        }
    }
    __syncthreads();

    {
        const int d  = tid >> 2;
        const int j0 = (tid & 3) * 8;
        float4 a0a = {0,0,0,0}, a0b = {0,0,0,0}, a1a = {0,0,0,0}, a1b = {0,0,0,0};
        for (int s = 0; s < 32; s++) {
            float a = kvs[s * 64 + d];
            const float4* pr = (const float4*)&ps[s * 32 + j0];
            float4 pa = pr[0], pb = pr[1];
            a0a.x += a * pa.x; a0a.y += a * pa.y; a0a.z += a * pa.z; a0a.w += a * pa.w;
            a0b.x += a * pb.x; a0b.y += a * pb.y; a0b.z += a * pb.z; a0b.w += a * pb.w;
        }
        for (int s = 32; s < 64; s++) {
            float a = kvs[s * 64 + d];
            const float4* pr = (const float4*)&ps[s * 32 + j0];
            float4 pa = pr[0], pb = pr[1];
            a1a.x += a * pa.x; a1a.y += a * pa.y; a1a.z += a * pa.z; a1a.w += a * pa.w;
            a1b.x += a * pb.x; a1b.y += a * pb.y; a1b.z += a * pb.z; a1b.w += a * pb.w;
        }
        float* o0 = &g_S[((size_t)bh * NSC + 2 * bx)     * 2048];
        float* o1 = &g_S[((size_t)bh * NSC + 2 * bx + 1) * 2048];
        ((float4*)&o0[d * 32 + j0])[0] = a0a;
        ((float4*)&o0[d * 32 + j0])[1] = a0b;
        ((float4*)&o1[d * 32 + j0])[0] = a1a;
        ((float4*)&o1[d * 32 + j0])[1] = a1b;
    }
}

// ------------------- exclusive prefix scan over 64 chunks ------------------
__global__ __launch_bounds__(256)
void scan_states()
{
    const int gi = blockIdx.x * 256 + threadIdx.x;
    const int bh = gi >> 11;
    const int e  = gi & 2047;
    float run = 0.f;
    float* p = &g_S[(size_t)bh * NSC * 2048 + e];
    for (int c = 0; c < NSC; c++) {
        float v = p[c * 2048];
        p[c * 2048] = run;
        run += v;
    }
}

// ------------------- fused pass1 + softmax + pass2 (float4 LDS) -------------
// strides: qs 68, kvs 64, ps 36, ws 36, ss 36, ssT 68.
__global__ __launch_bounds__(256, 2)
void fused_pass()
{
    const int bx = blockIdx.x, bh = blockIdx.y;
    extern __shared__ float sm[];
    float* qs  = sm;                 // 64 x 68
    float* kvs = qs  + 64 * 68;      // 64 x 64
    float* ps  = kvs + 64 * 64;      // 64 x 36
    float* ws  = ps  + 64 * 36;      // 64 x 36
    float* ss  = ws  + 64 * 36;      // 2 x 64 x 36
    float* ssT = ss  + 2 * 64 * 36;  // 2 x 32 x 68
    const size_t base = (size_t)bh * T_LEN + bx * 64;
    const int tid = threadIdx.x;

    for (int i = tid; i < 64 * 64; i += 256) {
        int s = i >> 6, d = i & 63;
        kvs[i] = g_kv[(base + s) * 64 + d];
        qs[s * 68 + d] = g_q[(base + s) * 64 + d];
    }
    for (int i = tid; i < 64 * 32; i += 256) {
        int s = i >> 5, j = i & 31;
        ps[s * 36 + j] = g_pattn[base * 32 + i];
    }
    for (int i = tid; i < 2 * 64 * 32; i += 256) {
        int ci  = i >> 11;
        int idx = i & 2047;
        int d = idx >> 5, j = idx & 31;
        float v = g_S[((size_t)bh * NSC + 2 * bx + ci) * 2048 + idx];
        ss [ci * (64 * 36) + d * 36 + j] = v;
        ssT[ci * (32 * 68) + j * 68 + d] = v;
    }
    __syncthreads();

    const int cid = tid >> 7;
    const int lt  = (tid >> 2) & 31;
    const int sub = tid & 3;
    const int row = cid * 32 + lt;
    const int tgl = bx * 64 + row;
    const float inv = 1.0f / (float)(tgl + 1);
    const int smax = lt | 7;
    const float* ssb  = ss  + cid * (64 * 36);
    const float* ssTb = ssT + cid * (32 * 68);
    const int srow0 = cid * 32;

    // ---------------- pass 1 ----------------
    {
        const int j0  = sub * 8;
        const int dq0 = sub * 16;
        float4 q4[4];
        const float4* qsp = (const float4*)&qs[row * 68 + dq0];
#pragma unroll
        for (int k = 0; k < 4; k++) q4[k] = qsp[k];

        float r[8];
#pragma unroll
        for (int jj = 0; jj < 8; jj++) r[jj] = 0.f;

        // inter-chunk: q[t] @ S_prefix (float4 reads of ss rows)
        const float* qrow = &qs[row * 68];
#pragma unroll 8
        for (int d = 0; d < 64; d++) {
            float a = qrow[d];
            const float4* sr = (const float4*)&ssb[d * 36 + j0];
            float4 sa = sr[0], sb2 = sr[1];
            r[0] += a * sa.x;  r[1] += a * sa.y;  r[2] += a * sa.z;  r[3] += a * sa.w;
            r[4] += a * sb2.x; r[5] += a * sb2.y; r[6] += a * sb2.z; r[7] += a * sb2.w;
        }
        // intra-chunk causal (float4 dot, sub-lane split)
        for (int s = 0; s <= smax; s++) {
            const float4* kr = (const float4*)&kvs[(srow0 + s) * 64 + dq0];
            float a0 = 0.f, a1 = 0.f, a2 = 0.f, a3 = 0.f;
#pragma unroll
            for (int k = 0; k < 4; k++) {
                float4 k4 = kr[k];
                a0 += q4[k].x * k4.x;
                a1 += q4[k].y * k4.y;
                a2 += q4[k].z * k4.z;
                a3 += q4[k].w * k4.w;
            }
            float a = (a0 + a1) + (a2 + a3);
            a += __shfl_xor_sync(0xffffffffu, a, 1);
            a += __shfl_xor_sync(0xffffffffu, a, 2);
            if (s <= lt) {
                const float4* pr = (const float4*)&ps[(srow0 + s) * 36 + j0];
                float4 pa = pr[0], pb = pr[1];
                r[0] += a * pa.x; r[1] += a * pa.y; r[2] += a * pa.z; r[3] += a * pa.w;
                r[4] += a * pb.x; r[5] += a * pb.y; r[6] += a * pb.z; r[7] += a * pb.w;
            }
        }
        float mx = -1e30f;
#pragma unroll
        for (int jj = 0; jj < 8; jj++) { r[jj] *= inv; mx = fmaxf(mx, r[jj]); }
        mx = fmaxf(mx, __shfl_xor_sync(0xffffffffu, mx, 1));
        mx = fmaxf(mx, __shfl_xor_sync(0xffffffffu, mx, 2));
        float sum = 0.f;
#pragma unroll
        for (int jj = 0; jj < 8; jj++) { r[jj] = expf(r[jj] - mx); sum += r[jj]; }
        sum += __shfl_xor_sync(0xffffffffu, sum, 1);
        sum += __shfl_xor_sync(0xffffffffu, sum, 2);
        float rs = 1.0f / sum;
        float4 w0 = make_float4(r[0] * rs, r[1] * rs, r[2] * rs, r[3] * rs);
        float4 w1 = make_float4(r[4] * rs, r[5] * rs, r[6] * rs, r[7] * rs);
        ((float4*)&ws[row * 36 + j0])[0] = w0;
        ((float4*)&ws[row * 36 + j0])[1] = w1;
    }
    __syncwarp();

    // ---------------- pass 2 ----------------
    {
        const int d0 = sub * 16;
        const int jw0 = sub * 8;
        float4 w4[8];
        const float4* wsp = (const float4*)&ws[row * 36];
#pragma unroll
        for (int k = 0; k < 8; k++) w4[k] = wsp[k];
        const float* wreg = (const float*)w4;

        float r[16];
#pragma unroll
        for (int dd = 0; dd < 16; dd++) r[dd] = 0.f;

        // inter-chunk: w[t] @ S^T_prefix (float4 reads of ssT rows)
#pragma unroll 8
        for (int j = 0; j < 32; j++) {
            float a = wreg[j];
            const float4* sr = (const float4*)&ssTb[j * 68 + d0];
#pragma unroll
            for (int k = 0; k < 4; k++) {
                float4 s4 = sr[k];
                r[4 * k + 0] += a * s4.x;
                r[4 * k + 1] += a * s4.y;
                r[4 * k + 2] += a * s4.z;
                r[4 * k + 3] += a * s4.w;
            }
        }
        // intra-chunk causal
        const float4* wq = &w4[sub * 2];
        for (int s = 0; s <= smax; s++) {
            const float4* pr = (const float4*)&ps[(srow0 + s) * 36 + jw0];
            float4 pa = pr[0], pb = pr[1];
            float a0 = wq[0].x * pa.x + wq[0].y * pa.y + wq[0].z * pa.z + wq[0].w * pa.w;
            float a1 = wq[1].x * pb.x + wq[1].y * pb.y + wq[1].z * pb.z + wq[1].w * pb.w;
            float a = a0 + a1;
            a += __shfl_xor_sync(0xffffffffu, a, 1);
            a += __shfl_xor_sync(0xffffffffu, a, 2);
            if (s <= lt) {
                const float4* kr = (const float4*)&kvs[(srow0 + s) * 64 + d0];
#pragma unroll
                for (int k = 0; k < 4; k++) {
                    float4 k4 = kr[k];
                    r[4 * k + 0] += a * k4.x;
                    r[4 * k + 1] += a * k4.y;
                    r[4 * k + 2] += a * k4.z;
                    r[4 * k + 3] += a * k4.w;
                }
            }
        }
        const int b = bh >> 4, hh = bh & 15;
        const size_t ob = ((size_t)tgl * 2 + b) * 1024 + hh * 64 + d0;
        __half2 h2[8];
#pragma unroll
        for (int k = 0; k < 8; k++)
            h2[k] = __half2(__float2half_rn(r[2 * k] * inv), __float2half_rn(r[2 * k + 1] * inv));
        *(uint4*)&g_ATh[ob]     = *(uint4*)&h2[0];
        *(uint4*)&g_ATh[ob + 8] = *(uint4*)&h2[4];
    }
}

// ---------------------------------------------------------------------------
extern "C" void kernel_launch(void* const* d_in, const int* in_sizes, int n_in,
                              void* d_out, int out_size)
{
    const float* query  = (const float*)d_in[0];
    const float* pquery = (const float*)d_in[1];
    const float* Wpq = (const float*)d_in[2];
    const float* bpq = (const float*)d_in[3];
    const float* Wq  = (const float*)d_in[4];
    const float* bq  = (const float*)d_in[5];
    const float* Wpc = (const float*)d_in[6];
    const float* bpc = (const float*)d_in[7];
    const float* Wc  = (const float*)d_in[8];
    const float* bc  = (const float*)d_in[9];
    const float* Wo  = (const float*)d_in[10];
    const float* bo  = (const float*)d_in[11];
    float* out = (float*)d_out;

    float *p_pq, *p_q, *p_kp, *p_kv;
    __half *p_Ah, *p_PQh, *p_W4h, *p_WOh, *p_ATh;
    cudaGetSymbolAddress((void**)&p_pq,  g_pq);
    cudaGetSymbolAddress((void**)&p_q,   g_q);
    cudaGetSymbolAddress((void**)&p_kp,  g_kp);
    cudaGetSymbolAddress((void**)&p_kv,  g_kv);
    cudaGetSymbolAddress((void**)&p_Ah,  g_Ah);
    cudaGetSymbolAddress((void**)&p_PQh, g_PQh);
    cudaGetSymbolAddress((void**)&p_W4h, g_W4h);
    cudaGetSymbolAddress((void**)&p_WOh, g_WOh);
    cudaGetSymbolAddress((void**)&p_ATh, g_ATh);

    const int GEMM_SMEM = 3 * 32768;
    const int PL_SMEM = (64 * 68 + 32 * 68 + 64 * 64 + 64 * 32) * 4;                 // 50688
    const int FP_SMEM = (64 * 68 + 64 * 64 + 64 * 36 * 2 + 2 * 64 * 36 + 2 * 32 * 68) * 4; // 88064
    cudaFuncSetAttribute(gemm_mma,    cudaFuncAttributeMaxDynamicSharedMemorySize, GEMM_SMEM);
    cudaFuncSetAttribute(pattn_local, cudaFuncAttributeMaxDynamicSharedMemorySize, PL_SMEM);
    cudaFuncSetAttribute(fused_pass,  cudaFuncAttributeMaxDynamicSharedMemorySize, FP_SMEM);

    // ---- launch 0: dummy (shifts pattn_local into the profiled slot) ----
    dummy_k<<<1, 32>>>();

    // ---- launch 1: ALL conversions ----
    CvtArgs ca;
    int acc = 0, n4;
    n4 = MROWS * E_DIM / 4;
    ca.s[0] = (const float4*)query;  ca.h[0] = (__half2*)p_Ah;  acc += n4; ca.end[0] = acc;
    n4 = 64 * E_DIM / 4;
    ca.s[1] = (const float4*)pquery; ca.h[1] = (__half2*)p_PQh; acc += n4; ca.end[1] = acc;
    n4 = NE / 4;
    ca.s[2] = (const float4*)Wq;  ca.h[2] = (__half2*)p_W4h;            acc += n4; ca.end[2] = acc;
    ca.s[3] = (const float4*)Wpc; ca.h[3] = (__half2*)(p_W4h + NE);     acc += n4; ca.end[3] = acc;
    ca.s[4] = (const float4*)Wc;  ca.h[4] = (__half2*)(p_W4h + 2 * NE); acc += n4; ca.end[4] = acc;
    ca.s[5] = (const float4*)Wpq; ca.h[5] = (__half2*)(p_W4h + 3 * NE); acc += n4; ca.end[5] = acc;
    ca.s[6] = (const float4*)Wo;  ca.h[6] = (__half2*)p_WOh;            acc += n4; ca.end[6] = acc;
    cvt_all<<<(acc + 255) / 256, 256>>>(ca);

    // ---- launch 2: q/kp/kv/pq projections (z = 0..3) ----
    gemm_mma<<<dim3(8, 32, 4), 256, GEMM_SMEM>>>(
        p_Ah, p_PQh, p_W4h,
        bq, bpc, bc, bpq,
        p_q, p_kp, p_kv, p_pq,
        SCALING, 1.0f, 1.0f, SCALING,
        MROWS, 64, 1, T_LEN, PLEN);

    // ---- launch 3: pattn + local states  [profiled slot] ----
    pattn_local<<<dim3(T_LEN / 64, BH), 256, PL_SMEM>>>();

    // ---- launch 4: exclusive scan over 64 chunks ----
    scan_states<<<BH * 2048 / 256, 256>>>();

    // ---- launch 5: fused pass1 + softmax + pass2 ----
    fused_pass<<<dim3(T_LEN / 64, BH), 256, FP_SMEM>>>();

    // ---- launch 6: output projection -> d_out ----
    gemm_mma<<<dim3(8, 32, 1), 256, GEMM_SMEM>>>(
        p_ATh, p_ATh, p_WOh,
        bo, bo, bo, bo,
        out, out, out, out,
        1.0f, 1.0f, 1.0f, 1.0f,
        MROWS, MROWS, 0, 0, 0);
}

// round 15
// speedup vs baseline: 2.0208x; 2.0208x over previous
#include <cuda_runtime.h>
#include <cuda_fp16.h>
#include <math.h>
#include <stdint.h>

#define T_LEN  2048
#define BSZ    2
#define E_DIM  1024
#define H_NUM  16
#define D_DIM  64
#define PLEN   32
#define BH     32
#define SCH    32               // state chunk
#define NSC    (T_LEN/SCH)      // 64
#define SCALING 0.125f
#define BETA    0.6931471805599453f

#define MROWS  (T_LEN*BSZ)      // 4096
#define NE     (E_DIM*E_DIM)

// ------------------------- scratch -----------------------------------------
__device__ float g_pq   [BH*PLEN*D_DIM];
__device__ float g_q    [BH*T_LEN*D_DIM];
__device__ float g_kp   [BH*T_LEN*D_DIM];
__device__ float g_kv   [BH*T_LEN*D_DIM];
__device__ float g_pattn[BH*T_LEN*PLEN];
__device__ float g_S    [BH*NSC*D_DIM*PLEN];

__device__ __half g_Ah  [MROWS*E_DIM];
__device__ __half g_PQh [64*E_DIM];
__device__ __half g_W4h [4*NE];          // Wq, Wpc, Wc, Wpq
__device__ __half g_WOh [NE];
__device__ __half g_ATh [MROWS*E_DIM];

// ------------------------- helpers -----------------------------------------
__device__ __forceinline__ uint32_t smem_u32(const void* p) {
    uint32_t a;
    asm("{ .reg .u64 t; cvta.to.shared.u64 t, %1; cvt.u32.u64 %0, t; }"
        : "=r"(a) : "l"(p));
    return a;
}
__device__ __forceinline__ uint32_t sw128(uint32_t off) {
    return off ^ ((off >> 3) & 0x70);
}
__device__ __forceinline__ void ldsm_x4(uint32_t* r, uint32_t addr) {
    asm volatile("ldmatrix.sync.aligned.m8n8.x4.shared.b16 {%0,%1,%2,%3}, [%4];"
                 : "=r"(r[0]), "=r"(r[1]), "=r"(r[2]), "=r"(r[3]) : "r"(addr));
}
__device__ __forceinline__ void mma16816(float* c, const uint32_t* a, const uint32_t* b) {
    asm volatile("mma.sync.aligned.m16n8k16.row.col.f32.f16.f16.f32 "
                 "{%0,%1,%2,%3}, {%4,%5,%6,%7}, {%8,%9}, {%0,%1,%2,%3};"
                 : "+f"(c[0]), "+f"(c[1]), "+f"(c[2]), "+f"(c[3])
                 : "r"(a[0]), "r"(a[1]), "r"(a[2]), "r"(a[3]), "r"(b[0]), "r"(b[1]));
}
__device__ __forceinline__ void cp16(uint32_t dst, const void* src, int sz) {
    asm volatile("cp.async.cg.shared.global [%0], [%1], 16, %2;"
                 :: "r"(dst), "l"(src), "r"(sz));
}
__device__ __forceinline__ void cp_commit() {
    asm volatile("cp.async.commit_group;" ::: "memory");
}
__device__ __forceinline__ void cp_wait1() {
    asm volatile("cp.async.wait_group 1;" ::: "memory");
}
__device__ __forceinline__ void cp_wait0() {
    asm volatile("cp.async.wait_group 0;" ::: "memory");
}

// ------------------------- merged fp32 -> fp16 converter -------------------
#define NCVT 7
struct CvtArgs {
    const float4* s[NCVT];
    __half2*      h[NCVT];
    int           end[NCVT];
};

__global__ __launch_bounds__(256)
void cvt_all(CvtArgs A)
{
    int gi = blockIdx.x * 256 + threadIdx.x;
    int seg = 0;
    while (seg < NCVT && gi >= A.end[seg]) seg++;
    if (seg >= NCVT) return;
    int i = gi - (seg ? A.end[seg - 1] : 0);

    float4 v = A.s[seg][i];
    A.h[seg][2 * i]     = __half2(__float2half_rn(v.x), __float2half_rn(v.y));
    A.h[seg][2 * i + 1] = __half2(__float2half_rn(v.z), __float2half_rn(v.w));
}

// ------------------------- pipelined fp16 GEMM (R10 form) -------------------
__device__ __forceinline__ void g_load_stage(
    uint32_t sb, int slot,
    const __half* Ah, const __half* Bh,
    int bm, int bn, int kb, int M, int tid)
{
    const uint32_t abase = sb + slot * 32768;
    const uint32_t bbase = abase + 16384;
    const int c  = tid & 7;
    const int r0 = tid >> 3;
    const int kc = kb + c * 8;
#pragma unroll
    for (int ii = 0; ii < 4; ii++) {
        int r = r0 + ii * 32;
        uint32_t so = sw128((uint32_t)(r * 128 + c * 16));
        int m = bm + r;
        int mc = (m < M) ? m : (M - 1);
        cp16(abase + so, Ah + (size_t)mc * E_DIM + kc, (m < M) ? 16 : 0);
        cp16(bbase + so, Bh + (size_t)(bn + r) * E_DIM + kc, 16);
    }
}

__global__ __launch_bounds__(256, 2)
void gemm_mma(const __half* __restrict__ A0, const __half* __restrict__ A3,
              const __half* __restrict__ W,
              const float* b0, const float* b1, const float* b2, const float* b3,
              float* o0, float* o1, float* o2, float* o3,
              float s0, float s1, float s2, float s3,
              int M0, int M3, int mode, int Trows0, int Trows3)
{
    extern __shared__ char smem[];
    const uint32_t sb = smem_u32(smem);

    const int tid = threadIdx.x, wid = tid >> 5, lane = tid & 31;
    const int bm = blockIdx.y * 128, bn = blockIdx.x * 128;
    const int z = blockIdx.z;
    const int M     = (z == 3) ? M3 : M0;
    const int Trows = (z == 3) ? Trows3 : Trows0;
    if (bm >= M) return;
    const __half* Ah = (z == 3) ? A3 : A0;
    const __half* wh = W + (size_t)z * NE;
    const float* bias = (z == 0) ? b0 : ((z == 1) ? b1 : ((z == 2) ? b2 : b3));
    float* out        = (z == 0) ? o0 : ((z == 1) ? o1 : ((z == 2) ? o2 : o3));
    const float scale = (z == 0) ? s0 : ((z == 1) ? s1 : ((z == 2) ? s2 : s3));

    const int warpM = (wid >> 2) * 64;
    const int warpN = (wid & 3) * 32;
    const int li = lane >> 3, lr = lane & 7;

    float acc[4][4][4];
#pragma unroll
    for (int i = 0; i < 4; i++)
#pragma unroll
        for (int j = 0; j < 4; j++)
#pragma unroll
            for (int k = 0; k < 4; k++) acc[i][j][k] = 0.f;

    const int NK = E_DIM / 64;
    g_load_stage(sb, 0, Ah, wh, bm, bn, 0, M, tid);
    cp_commit();
    g_load_stage(sb, 1, Ah, wh, bm, bn, 64, M, tid);
    cp_commit();

    int slot = 0, next = 2;
    for (int ks = 0; ks < NK; ks++) {
        if (ks + 1 < NK) cp_wait1(); else cp_wait0();
        __syncthreads();
        if (ks + 2 < NK) {
            g_load_stage(sb, next, Ah, wh, bm, bn, (ks + 2) * 64, M, tid);
            cp_commit();
            if (++next == 3) next = 0;
        }

        const uint32_t abase = sb + slot * 32768;
        const uint32_t bbase = abase + 16384;
        if (++slot == 3) slot = 0;
#pragma unroll
        for (int kk = 0; kk < 4; kk++) {
            uint32_t bfr[2][4];
            const uint32_t kb2 = (uint32_t)(kk * 32 + (li & 1) * 16);
#pragma unroll
            for (int jn = 0; jn < 2; jn++) {
                uint32_t off = (uint32_t)((warpN + jn * 16 + (li >> 1) * 8 + lr) * 128) + kb2;
                ldsm_x4(bfr[jn], bbase + sw128(off));
            }
            const uint32_t ka = (uint32_t)(kk * 32 + (li >> 1) * 16);
#pragma unroll
            for (int i = 0; i < 4; i++) {
                uint32_t ah[4];
                uint32_t off = (uint32_t)((warpM + i * 16 + (li & 1) * 8 + lr) * 128) + ka;
                ldsm_x4(ah, abase + sw128(off));
#pragma unroll
                for (int j = 0; j < 4; j++)
                    mma16816(acc[i][j], ah, &bfr[j >> 1][(j & 1) * 2]);
            }
        }
    }

    const int g = lane >> 2, tg = lane & 3;
#pragma unroll
    for (int i = 0; i < 4; i++) {
#pragma unroll
        for (int j = 0; j < 4; j++) {
            int n0 = bn + warpN + j * 8 + tg * 2;
            float bx = bias[n0], by = bias[n0 + 1];
#pragma unroll
            for (int half = 0; half < 2; half++) {
                int m = bm + warpM + i * 16 + g + half * 8;
                if (m >= M) continue;
                float2 v;
                v.x = (acc[i][j][half * 2 + 0] + bx) * scale;
                v.y = (acc[i][j][half * 2 + 1] + by) * scale;
                if (mode == 0) {
                    *(float2*)&out[(size_t)m * E_DIM + n0] = v;
                } else {
                    int t = m >> 1, b = m & 1;
                    int h = n0 >> 6, d = n0 & 63;
                    *(float2*)&out[(size_t)((b * 16 + h) * Trows + t) * 64 + d] = v;
                }
            }
        }
    }
}

// ------------- merged pattn (softplus) + TWO 32-row local states ------------
// R10 compute; float4 global loads/stores only.
__global__ __launch_bounds__(256, 2)
void pattn_local()
{
    const int bx = blockIdx.x, bh = blockIdx.y;
    extern __shared__ float sm[];
    float* kps = sm;                   // 64 x 65
    float* pqs = kps + 64 * 65;        // 32 x 65
    float* kvs = pqs + 32 * 65;        // 64 x 64
    float* ps  = kvs + 64 * 64;        // 64 x 32
    const size_t base = (size_t)bh * T_LEN + bx * 64;
    const int tid = threadIdx.x;

    for (int i = tid; i < 64 * 16; i += 256) {
        int s = i >> 4, d4 = i & 15;
        float4 kp4 = ((const float4*)(g_kp + (base + s) * 64))[d4];
        float* kd = kps + s * 65 + d4 * 4;
        kd[0] = kp4.x; kd[1] = kp4.y; kd[2] = kp4.z; kd[3] = kp4.w;
        float4 kv4 = ((const float4*)(g_kv + (base + s) * 64))[d4];
        ((float4*)(kvs + s * 64))[d4] = kv4;
    }
    for (int i = tid; i < PLEN * 16; i += 256) {
        int p = i >> 4, d4 = i & 15;
        float4 v = ((const float4*)(g_pq + (size_t)bh * PLEN * D_DIM + p * 64))[d4];
        float* pd = pqs + p * 65 + d4 * 4;
        pd[0] = v.x; pd[1] = v.y; pd[2] = v.z; pd[3] = v.w;
    }
    __syncthreads();

    {
        const int t  = tid >> 2;
        const int p0 = (tid & 3) * 8;
        float tmp[8];
#pragma unroll
        for (int pp = 0; pp < 8; pp++) {
            int p = p0 + pp;
            float a0 = 0.f, a1 = 0.f, a2 = 0.f, a3 = 0.f;
#pragma unroll
            for (int d = 0; d < 64; d += 4) {
                a0 += kps[t * 65 + d]     * pqs[p * 65 + d];
                a1 += kps[t * 65 + d + 1] * pqs[p * 65 + d + 1];
                a2 += kps[t * 65 + d + 2] * pqs[p * 65 + d + 2];
                a3 += kps[t * 65 + d + 3] * pqs[p * 65 + d + 3];
            }
            float accv = (a0 + a1) + (a2 + a3);
            float zz = BETA * accv;
            float sp = (fmaxf(zz, 0.f) + log1pf(expf(-fabsf(zz)))) * (1.0f / BETA);
            ps[t * 32 + p] = sp;
            tmp[pp] = sp;
        }
        float* gp = (float*)&g_pattn[(base + t) * PLEN + p0];
        ((float4*)gp)[0] = make_float4(tmp[0], tmp[1], tmp[2], tmp[3]);
        ((float4*)gp)[1] = make_float4(tmp[4], tmp[5], tmp[6], tmp[7]);
    }
    __syncthreads();

    {
        const int d  = tid >> 2;
        const int j0 = (tid & 3) * 8;
        float acc0[8] = {0.f}, acc1[8] = {0.f};
        for (int s = 0; s < 32; s++) {
            float a = kvs[s * 64 + d];
#pragma unroll
            for (int jj = 0; jj < 8; jj++) acc0[jj] += a * ps[s * 32 + j0 + jj];
        }
        for (int s = 32; s < 64; s++) {
            float a = kvs[s * 64 + d];
#pragma unroll
            for (int jj = 0; jj < 8; jj++) acc1[jj] += a * ps[s * 32 + j0 + jj];
        }
        float* o0 = &g_S[((size_t)bh * NSC + 2 * bx)     * 2048 + d * 32 + j0];
        float* o1 = &g_S[((size_t)bh * NSC + 2 * bx + 1) * 2048 + d * 32 + j0];
        ((float4*)o0)[0] = make_float4(acc0[0], acc0[1], acc0[2], acc0[3]);
        ((float4*)o0)[1] = make_float4(acc0[4], acc0[5], acc0[6], acc0[7]);
        ((float4*)o1)[0] = make_float4(acc1[0], acc1[1], acc1[2], acc1[3]);
        ((float4*)o1)[1] = make_float4(acc1[4], acc1[5], acc1[6], acc1[7]);
    }
}

// ------------------- exclusive prefix scan over 64 chunks ------------------
__global__ __launch_bounds__(256)
void scan_states()
{
    const int gi = blockIdx.x * 256 + threadIdx.x;
    const int bh = gi >> 11;
    const int e  = gi & 2047;
    float run = 0.f;
    float* p = &g_S[(size_t)bh * NSC * 2048 + e];
    for (int c = 0; c < NSC; c++) {
        float v = p[c * 2048];
        p[c * 2048] = run;
        run += v;
    }
}

// ------------------- fused pass1 + softmax + pass2 (R10 compute) ------------
__global__ __launch_bounds__(256, 2)
void fused_pass()
{
    const int bx = blockIdx.x, bh = blockIdx.y;
    extern __shared__ float sm[];
    float* qs  = sm;                 // 64 x 65
    float* kvs = qs  + 64 * 65;      // 64 x 64
    float* ps  = kvs + 64 * 64;      // 64 x 33
    float* ws  = ps  + 64 * 33;      // 64 x 33
    float* ss  = ws  + 64 * 33;      // 2 x 64 x 33
    float* ssT = ss  + 2 * 64 * 33;  // 2 x 32 x 65
    const size_t base = (size_t)bh * T_LEN + bx * 64;
    const int tid = threadIdx.x;

    for (int i = tid; i < 64 * 16; i += 256) {
        int s = i >> 4, d4 = i & 15;
        float4 kv4 = ((const float4*)(g_kv + (base + s) * 64))[d4];
        ((float4*)(kvs + s * 64))[d4] = kv4;
        float4 q4 = ((const float4*)(g_q + (base + s) * 64))[d4];
        float* qd = qs + s * 65 + d4 * 4;
        qd[0] = q4.x; qd[1] = q4.y; qd[2] = q4.z; qd[3] = q4.w;
    }
    for (int i = tid; i < 64 * 8; i += 256) {
        int s = i >> 3, j4 = i & 7;
        float4 p4 = ((const float4*)(g_pattn + (base + s) * 32))[j4];
        float* pd = ps + s * 33 + j4 * 4;
        pd[0] = p4.x; pd[1] = p4.y; pd[2] = p4.z; pd[3] = p4.w;
    }
    for (int i = tid; i < 2 * 64 * 8; i += 256) {
        int ci   = i >> 9;
        int idx4 = i & 511;
        int d = idx4 >> 3, j4 = idx4 & 7;
        float4 v = ((const float4*)(g_S + ((size_t)bh * NSC + 2 * bx + ci) * 2048))[idx4];
        float* sd = ss + ci * (64 * 33) + d * 33 + j4 * 4;
        sd[0] = v.x; sd[1] = v.y; sd[2] = v.z; sd[3] = v.w;
        float* st = ssT + ci * (32 * 65);
        int j0 = j4 * 4;
        st[(j0 + 0) * 65 + d] = v.x;
        st[(j0 + 1) * 65 + d] = v.y;
        st[(j0 + 2) * 65 + d] = v.z;
        st[(j0 + 3) * 65 + d] = v.w;
    }
    __syncthreads();

    const int cid = tid >> 7;
    const int lt  = (tid >> 2) & 31;
    const int sub = tid & 3;
    const int row = cid * 32 + lt;
    const int tgl = bx * 64 + row;
    const float inv = 1.0f / (float)(tgl + 1);
    const int smax = lt | 7;
    const float* ssb  = ss  + cid * (64 * 33);
    const float* ssTb = ssT + cid * (32 * 65);
    const int srow0 = cid * 32;

    // ---------------- pass 1 ----------------
    {
        const int j0  = sub * 8;
        const int dq0 = sub * 16;
        float qreg[16];
#pragma unroll
        for (int d = 0; d < 16; d++) qreg[d] = qs[row * 65 + dq0 + d];

        float r[8];
#pragma unroll
        for (int jj = 0; jj < 8; jj++) r[jj] = 0.f;

        const float* qrow = &qs[row * 65];
#pragma unroll 8
        for (int d = 0; d < 64; d++) {
            float a = qrow[d];
#pragma unroll
            for (int jj = 0; jj < 8; jj++) r[jj] += a * ssb[d * 33 + j0 + jj];
        }
        for (int s = 0; s <= smax; s++) {
            const float* kr = &kvs[(srow0 + s) * 64 + dq0];
            float a0 = 0.f, a1 = 0.f, a2 = 0.f, a3 = 0.f;
#pragma unroll
            for (int d = 0; d < 16; d += 4) {
                a0 += qreg[d]     * kr[d];
                a1 += qreg[d + 1] * kr[d + 1];
                a2 += qreg[d + 2] * kr[d + 2];
                a3 += qreg[d + 3] * kr[d + 3];
            }
            float a = (a0 + a1) + (a2 + a3);
            a += __shfl_xor_sync(0xffffffffu, a, 1);
            a += __shfl_xor_sync(0xffffffffu, a, 2);
            if (s <= lt) {
                const float* pr = &ps[(srow0 + s) * 33 + j0];
#pragma unroll
                for (int jj = 0; jj < 8; jj++) r[jj] += a * pr[jj];
            }
        }
        float mx = -1e30f;
#pragma unroll
        for (int jj = 0; jj < 8; jj++) { r[jj] *= inv; mx = fmaxf(mx, r[jj]); }
        mx = fmaxf(mx, __shfl_xor_sync(0xffffffffu, mx, 1));
        mx = fmaxf(mx, __shfl_xor_sync(0xffffffffu, mx, 2));
        float sum = 0.f;
#pragma unroll
        for (int jj = 0; jj < 8; jj++) { r[jj] = expf(r[jj] - mx); sum += r[jj]; }
        sum += __shfl_xor_sync(0xffffffffu, sum, 1);
        sum += __shfl_xor_sync(0xffffffffu, sum, 2);
        float rs = 1.0f / sum;
#pragma unroll
        for (int jj = 0; jj < 8; jj++) ws[row * 33 + j0 + jj] = r[jj] * rs;
    }
    __syncwarp();

    // ---------------- pass 2 ----------------
    {
        const int d0 = sub * 16;
        const int jw0 = sub * 8;
        float wreg[32];
#pragma unroll
        for (int j = 0; j < 32; j++) wreg[j] = ws[row * 33 + j];

        float r[16];
#pragma unroll
        for (int dd = 0; dd < 16; dd++) r[dd] = 0.f;

#pragma unroll 8
        for (int j = 0; j < 32; j++) {
            float a = wreg[j];
            const float* sr = &ssTb[j * 65 + d0];
#pragma unroll
            for (int dd = 0; dd < 16; dd++) r[dd] += a * sr[dd];
        }
        for (int s = 0; s <= smax; s++) {
            const float* pr = &ps[(srow0 + s) * 33 + jw0];
            float a0 = 0.f, a1 = 0.f;
#pragma unroll
            for (int j = 0; j < 8; j += 2) {
                a0 += wreg[jw0 + j]     * pr[j];
                a1 += wreg[jw0 + j + 1] * pr[j + 1];
            }
            float a = a0 + a1;
            a += __shfl_xor_sync(0xffffffffu, a, 1);
            a += __shfl_xor_sync(0xffffffffu, a, 2);
            if (s <= lt) {
                const float* kr = &kvs[(srow0 + s) * 64 + d0];
#pragma unroll
                for (int dd = 0; dd < 16; dd++) r[dd] += a * kr[dd];
            }
        }
        const int b = bh >> 4, hh = bh & 15;
        const size_t ob = ((size_t)tgl * 2 + b) * 1024 + hh * 64 + d0;
        __half2 h2[8];
#pragma unroll
        for (int k = 0; k < 8; k++)
            h2[k] = __half2(__float2half_rn(r[2 * k] * inv), __float2half_rn(r[2 * k + 1] * inv));
        *(uint4*)&g_ATh[ob]     = *(uint4*)&h2[0];
        *(uint4*)&g_ATh[ob + 8] = *(uint4*)&h2[4];
    }
}

// ---------------------------------------------------------------------------
extern "C" void kernel_launch(void* const* d_in, const int* in_sizes, int n_in,
                              void* d_out, int out_size)
{
    const float* query  = (const float*)d_in[0];
    const float* pquery = (const float*)d_in[1];
    const float* Wpq = (const float*)d_in[2];
    const float* bpq = (const float*)d_in[3];
    const float* Wq  = (const float*)d_in[4];
    const float* bq  = (const float*)d_in[5];
    const float* Wpc = (const float*)d_in[6];
    const float* bpc = (const float*)d_in[7];
    const float* Wc  = (const float*)d_in[8];
    const float* bc  = (const float*)d_in[9];
    const float* Wo  = (const float*)d_in[10];
    const float* bo  = (const float*)d_in[11];
    float* out = (float*)d_out;

    float *p_pq, *p_q, *p_kp, *p_kv;
    __half *p_Ah, *p_PQh, *p_W4h, *p_WOh, *p_ATh;
    cudaGetSymbolAddress((void**)&p_pq,  g_pq);
    cudaGetSymbolAddress((void**)&p_q,   g_q);
    cudaGetSymbolAddress((void**)&p_kp,  g_kp);
    cudaGetSymbolAddress((void**)&p_kv,  g_kv);
    cudaGetSymbolAddress((void**)&p_Ah,  g_Ah);
    cudaGetSymbolAddress((void**)&p_PQh, g_PQh);
    cudaGetSymbolAddress((void**)&p_W4h, g_W4h);
    cudaGetSymbolAddress((void**)&p_WOh, g_WOh);
    cudaGetSymbolAddress((void**)&p_ATh, g_ATh);

    const int GEMM_SMEM = 3 * 32768;
    const int PL_SMEM = (64 * 65 + 32 * 65 + 64 * 64 + 64 * 32) * 4;
    const int FP_SMEM = (64 * 65 + 64 * 64 + 64 * 33 + 64 * 33 + 2 * 64 * 33 + 2 * 32 * 65) * 4;
    cudaFuncSetAttribute(gemm_mma,    cudaFuncAttributeMaxDynamicSharedMemorySize, GEMM_SMEM);
    cudaFuncSetAttribute(pattn_local, cudaFuncAttributeMaxDynamicSharedMemorySize, PL_SMEM);
    cudaFuncSetAttribute(fused_pass,  cudaFuncAttributeMaxDynamicSharedMemorySize, FP_SMEM);

    // ---- launch 0: ALL conversions ----
    CvtArgs ca;
    int acc = 0, n4;
    n4 = MROWS * E_DIM / 4;
    ca.s[0] = (const float4*)query;  ca.h[0] = (__half2*)p_Ah;  acc += n4; ca.end[0] = acc;
    n4 = 64 * E_DIM / 4;
    ca.s[1] = (const float4*)pquery; ca.h[1] = (__half2*)p_PQh; acc += n4; ca.end[1] = acc;
    n4 = NE / 4;
    ca.s[2] = (const float4*)Wq;  ca.h[2] = (__half2*)p_W4h;            acc += n4; ca.end[2] = acc;
    ca.s[3] = (const float4*)Wpc; ca.h[3] = (__half2*)(p_W4h + NE);     acc += n4; ca.end[3] = acc;
    ca.s[4] = (const float4*)Wc;  ca.h[4] = (__half2*)(p_W4h + 2 * NE); acc += n4; ca.end[4] = acc;
    ca.s[5] = (const float4*)Wpq; ca.h[5] = (__half2*)(p_W4h + 3 * NE); acc += n4; ca.end[5] = acc;
    ca.s[6] = (const float4*)Wo;  ca.h[6] = (__half2*)p_WOh;            acc += n4; ca.end[6] = acc;
    cvt_all<<<(acc + 255) / 256, 256>>>(ca);

    // ---- launch 1: q/kp/kv/pq projections (z = 0..3) ----
    gemm_mma<<<dim3(8, 32, 4), 256, GEMM_SMEM>>>(
        p_Ah, p_PQh, p_W4h,
        bq, bpc, bc, bpq,
        p_q, p_kp, p_kv, p_pq,
        SCALING, 1.0f, 1.0f, SCALING,
        MROWS, 64, 1, T_LEN, PLEN);

    // ---- launch 2: pattn + two 32-row local states per block ----
    pattn_local<<<dim3(T_LEN / 64, BH), 256, PL_SMEM>>>();

    // ---- launch 3: exclusive scan over 64 chunks ----
    scan_states<<<BH * 2048 / 256, 256>>>();

    // ---- launch 4: fused pass1 + softmax + pass2 ----
    fused_pass<<<dim3(T_LEN / 64, BH), 256, FP_SMEM>>>();

    // ---- launch 5: output projection -> d_out ----
    gemm_mma<<<dim3(8, 32, 1), 256, GEMM_SMEM>>>(
        p_ATh, p_ATh, p_WOh,
        bo, bo, bo, bo,
        out, out, out, out,
        1.0f, 1.0f, 1.0f, 1.0f,
        MROWS, MROWS, 0, 0, 0);
}

// round 16
// speedup vs baseline: 2.1925x; 1.0850x over previous
#include <cuda_runtime.h>
#include <cuda_fp16.h>
#include <math.h>
#include <stdint.h>

#define T_LEN  2048
#define BSZ    2
#define E_DIM  1024
#define H_NUM  16
#define D_DIM  64
#define PLEN   32
#define BH     32
#define SCH    32               // state chunk
#define NSC    (T_LEN/SCH)      // 64
#define SCALING 0.125f
#define BETA    0.6931471805599453f

#define MROWS  (T_LEN*BSZ)      // 4096
#define NE     (E_DIM*E_DIM)

// ------------------------- scratch -----------------------------------------
__device__ float g_pq   [BH*PLEN*D_DIM];
__device__ float g_q    [BH*T_LEN*D_DIM];
__device__ float g_kp   [BH*T_LEN*D_DIM];
__device__ float g_kv   [BH*T_LEN*D_DIM];
__device__ float g_pattn[BH*T_LEN*PLEN];
__device__ float g_S    [BH*NSC*D_DIM*PLEN];

__device__ __half g_Ah  [MROWS*E_DIM];
__device__ __half g_PQh [64*E_DIM];
__device__ __half g_W4h [4*NE];          // Wq, Wpc, Wc, Wpq
__device__ __half g_WOh [NE];
__device__ __half g_ATh [MROWS*E_DIM];

// ------------------------- helpers -----------------------------------------
__device__ __forceinline__ uint32_t smem_u32(const void* p) {
    uint32_t a;
    asm("{ .reg .u64 t; cvta.to.shared.u64 t, %1; cvt.u32.u64 %0, t; }"
        : "=r"(a) : "l"(p));
    return a;
}
__device__ __forceinline__ uint32_t sw128(uint32_t off) {
    return off ^ ((off >> 3) & 0x70);
}
__device__ __forceinline__ void ldsm_x4(uint32_t* r, uint32_t addr) {
    asm volatile("ldmatrix.sync.aligned.m8n8.x4.shared.b16 {%0,%1,%2,%3}, [%4];"
                 : "=r"(r[0]), "=r"(r[1]), "=r"(r[2]), "=r"(r[3]) : "r"(addr));
}
__device__ __forceinline__ void mma16816(float* c, const uint32_t* a, const uint32_t* b) {
    asm volatile("mma.sync.aligned.m16n8k16.row.col.f32.f16.f16.f32 "
                 "{%0,%1,%2,%3}, {%4,%5,%6,%7}, {%8,%9}, {%0,%1,%2,%3};"
                 : "+f"(c[0]), "+f"(c[1]), "+f"(c[2]), "+f"(c[3])
                 : "r"(a[0]), "r"(a[1]), "r"(a[2]), "r"(a[3]), "r"(b[0]), "r"(b[1]));
}
__device__ __forceinline__ void cp16(uint32_t dst, const void* src, int sz) {
    asm volatile("cp.async.cg.shared.global [%0], [%1], 16, %2;"
                 :: "r"(dst), "l"(src), "r"(sz));
}
__device__ __forceinline__ void cp_commit() {
    asm volatile("cp.async.commit_group;" ::: "memory");
}
__device__ __forceinline__ void cp_wait1() {
    asm volatile("cp.async.wait_group 1;" ::: "memory");
}
__device__ __forceinline__ void cp_wait0() {
    asm volatile("cp.async.wait_group 0;" ::: "memory");
}
__device__ __forceinline__ float softplus_b(float accv) {
    float zz = BETA * accv;
    return (fmaxf(zz, 0.f) + log1pf(expf(-fabsf(zz)))) * (1.0f / BETA);
}

// ------------------------- merged fp32 -> fp16 converter -------------------
#define NCVT 7
struct CvtArgs {
    const float4* s[NCVT];
    __half2*      h[NCVT];
    int           end[NCVT];
};

__global__ __launch_bounds__(256)
void cvt_all(CvtArgs A)
{
    int gi = blockIdx.x * 256 + threadIdx.x;
    int seg = 0;
    while (seg < NCVT && gi >= A.end[seg]) seg++;
    if (seg >= NCVT) return;
    int i = gi - (seg ? A.end[seg - 1] : 0);

    float4 v = A.s[seg][i];
    A.h[seg][2 * i]     = __half2(__float2half_rn(v.x), __float2half_rn(v.y));
    A.h[seg][2 * i + 1] = __half2(__float2half_rn(v.z), __float2half_rn(v.w));
}

// ------------------------- pipelined fp16 GEMM (R10 form) -------------------
__device__ __forceinline__ void g_load_stage(
    uint32_t sb, int slot,
    const __half* Ah, const __half* Bh,
    int bm, int bn, int kb, int M, int tid)
{
    const uint32_t abase = sb + slot * 32768;
    const uint32_t bbase = abase + 16384;
    const int c  = tid & 7;
    const int r0 = tid >> 3;
    const int kc = kb + c * 8;
#pragma unroll
    for (int ii = 0; ii < 4; ii++) {
        int r = r0 + ii * 32;
        uint32_t so = sw128((uint32_t)(r * 128 + c * 16));
        int m = bm + r;
        int mc = (m < M) ? m : (M - 1);
        cp16(abase + so, Ah + (size_t)mc * E_DIM + kc, (m < M) ? 16 : 0);
        cp16(bbase + so, Bh + (size_t)(bn + r) * E_DIM + kc, 16);
    }
}

__global__ __launch_bounds__(256, 2)
void gemm_mma(const __half* __restrict__ A0, const __half* __restrict__ A3,
              const __half* __restrict__ W,
              const float* b0, const float* b1, const float* b2, const float* b3,
              float* o0, float* o1, float* o2, float* o3,
              float s0, float s1, float s2, float s3,
              int M0, int M3, int mode, int Trows0, int Trows3)
{
    extern __shared__ char smem[];
    const uint32_t sb = smem_u32(smem);

    const int tid = threadIdx.x, wid = tid >> 5, lane = tid & 31;
    const int bm = blockIdx.y * 128, bn = blockIdx.x * 128;
    const int z = blockIdx.z;
    const int M     = (z == 3) ? M3 : M0;
    const int Trows = (z == 3) ? Trows3 : Trows0;
    if (bm >= M) return;
    const __half* Ah = (z == 3) ? A3 : A0;
    const __half* wh = W + (size_t)z * NE;
    const float* bias = (z == 0) ? b0 : ((z == 1) ? b1 : ((z == 2) ? b2 : b3));
    float* out        = (z == 0) ? o0 : ((z == 1) ? o1 : ((z == 2) ? o2 : o3));
    const float scale = (z == 0) ? s0 : ((z == 1) ? s1 : ((z == 2) ? s2 : s3));

    const int warpM = (wid >> 2) * 64;
    const int warpN = (wid & 3) * 32;
    const int li = lane >> 3, lr = lane & 7;

    float acc[4][4][4];
#pragma unroll
    for (int i = 0; i < 4; i++)
#pragma unroll
        for (int j = 0; j < 4; j++)
#pragma unroll
            for (int k = 0; k < 4; k++) acc[i][j][k] = 0.f;

    const int NK = E_DIM / 64;
    g_load_stage(sb, 0, Ah, wh, bm, bn, 0, M, tid);
    cp_commit();
    g_load_stage(sb, 1, Ah, wh, bm, bn, 64, M, tid);
    cp_commit();

    int slot = 0, next = 2;
    for (int ks = 0; ks < NK; ks++) {
        if (ks + 1 < NK) cp_wait1(); else cp_wait0();
        __syncthreads();
        if (ks + 2 < NK) {
            g_load_stage(sb, next, Ah, wh, bm, bn, (ks + 2) * 64, M, tid);
            cp_commit();
            if (++next == 3) next = 0;
        }

        const uint32_t abase = sb + slot * 32768;
        const uint32_t bbase = abase + 16384;
        if (++slot == 3) slot = 0;
#pragma unroll
        for (int kk = 0; kk < 4; kk++) {
            uint32_t bfr[2][4];
            const uint32_t kb2 = (uint32_t)(kk * 32 + (li & 1) * 16);
#pragma unroll
            for (int jn = 0; jn < 2; jn++) {
                uint32_t off = (uint32_t)((warpN + jn * 16 + (li >> 1) * 8 + lr) * 128) + kb2;
                ldsm_x4(bfr[jn], bbase + sw128(off));
            }
            const uint32_t ka = (uint32_t)(kk * 32 + (li >> 1) * 16);
#pragma unroll
            for (int i = 0; i < 4; i++) {
                uint32_t ah[4];
                uint32_t off = (uint32_t)((warpM + i * 16 + (li & 1) * 8 + lr) * 128) + ka;
                ldsm_x4(ah, abase + sw128(off));
#pragma unroll
                for (int j = 0; j < 4; j++)
                    mma16816(acc[i][j], ah, &bfr[j >> 1][(j & 1) * 2]);
            }
        }
    }

    const int g = lane >> 2, tg = lane & 3;
#pragma unroll
    for (int i = 0; i < 4; i++) {
#pragma unroll
        for (int j = 0; j < 4; j++) {
            int n0 = bn + warpN + j * 8 + tg * 2;
            float bx = bias[n0], by = bias[n0 + 1];
#pragma unroll
            for (int half = 0; half < 2; half++) {
                int m = bm + warpM + i * 16 + g + half * 8;
                if (m >= M) continue;
                float2 v;
                v.x = (acc[i][j][half * 2 + 0] + bx) * scale;
                v.y = (acc[i][j][half * 2 + 1] + by) * scale;
                if (mode == 0) {
                    *(float2*)&out[(size_t)m * E_DIM + n0] = v;
                } else {
                    int t = m >> 1, b = m & 1;
                    int h = n0 >> 6, d = n0 & 63;
                    *(float2*)&out[(size_t)((b * 16 + h) * Trows + t) * 64 + d] = v;
                }
            }
        }
    }
}

// ------------- HMMA pattn (softplus) + TWO 32-row local states --------------
// 128 threads, 4 warps. Phase 1: pattn = softplus(KP @ PQ^T) per 16-row warp
// tile (fp16 mma, fp32 acc). Phase 2: S_c = KV^T @ P per chunk (P fp16-rounded).
__global__ __launch_bounds__(128, 4)
void pattn_local()
{
    const int bx = blockIdx.x, bh = blockIdx.y;
    extern __shared__ char smc[];
    __half* kph  = (__half*)smc;            // 64 x 72  (kp rows, d contiguous)
    __half* pqh  = kph + 64 * 72;           // 32 x 72  (pq rows, d contiguous)
    __half* kvTh = pqh + 32 * 72;           // 2 x 64 x 40  [cid][d][s]
    __half* pTh  = kvTh + 2 * 64 * 40;      // 2 x 32 x 40  [cid][p][s]
    const size_t base = (size_t)bh * T_LEN + bx * 64;
    const int tid = threadIdx.x;
    const int wid = tid >> 5, lane = tid & 31;
    const int li = lane >> 3, lr = lane & 7;
    const int g = lane >> 2, tg = lane & 3;

    // ---- stage fp32 -> fp16 ----
    for (int i = tid; i < 64 * 16; i += 128) {
        int s = i >> 4, d4 = i & 15;
        float4 kp4 = ((const float4*)(g_kp + (base + s) * 64))[d4];
        __half* kd = kph + s * 72 + d4 * 4;
        kd[0] = __float2half_rn(kp4.x); kd[1] = __float2half_rn(kp4.y);
        kd[2] = __float2half_rn(kp4.z); kd[3] = __float2half_rn(kp4.w);
        float4 kv4 = ((const float4*)(g_kv + (base + s) * 64))[d4];
        int cid = s >> 5, sl = s & 31;
        __half* kt = kvTh + cid * (64 * 40) + (d4 * 4) * 40 + sl;
        kt[0]   = __float2half_rn(kv4.x);
        kt[40]  = __float2half_rn(kv4.y);
        kt[80]  = __float2half_rn(kv4.z);
        kt[120] = __float2half_rn(kv4.w);
    }
    for (int i = tid; i < 32 * 16; i += 128) {
        int p = i >> 4, d4 = i & 15;
        float4 v = ((const float4*)(g_pq + (size_t)bh * PLEN * D_DIM + p * 64))[d4];
        __half* pd = pqh + p * 72 + d4 * 4;
        pd[0] = __float2half_rn(v.x); pd[1] = __float2half_rn(v.y);
        pd[2] = __float2half_rn(v.z); pd[3] = __float2half_rn(v.w);
    }
    __syncthreads();

    const uint32_t sb  = smem_u32(smc);
    const uint32_t KPH = 0;
    const uint32_t PQH = 64 * 72 * 2;
    const uint32_t KVT = PQH + 32 * 72 * 2;
    const uint32_t PTH = KVT + 2 * 64 * 40 * 2;

    // ---- phase 1: pattn rows wid*16 .. wid*16+16 ----
    {
        float pc[4][4];
#pragma unroll
        for (int jt = 0; jt < 4; jt++)
#pragma unroll
            for (int e = 0; e < 4; e++) pc[jt][e] = 0.f;

        uint32_t aq[4][4];
#pragma unroll
        for (int kk = 0; kk < 4; kk++) {
            uint32_t addr = sb + KPH
                + (uint32_t)((wid * 16 + (li & 1) * 8 + lr) * 144)
                + (uint32_t)(kk * 32 + (li >> 1) * 16);
            ldsm_x4(aq[kk], addr);
        }
#pragma unroll
        for (int kk = 0; kk < 4; kk++) {
            uint32_t bq[2][4];
#pragma unroll
            for (int jn = 0; jn < 2; jn++) {
                uint32_t addr = sb + PQH
                    + (uint32_t)((jn * 16 + (li >> 1) * 8 + lr) * 144)
                    + (uint32_t)(kk * 32 + (li & 1) * 16);
                ldsm_x4(bq[jn], addr);
            }
#pragma unroll
            for (int jt = 0; jt < 4; jt++)
                mma16816(pc[jt], aq[kk], &bq[jt >> 1][(jt & 1) * 2]);
        }

        const int trow = wid * 16 + g;         // block-local rows trow, trow+8
        const int cid  = wid >> 1;
        const int sl   = trow & 31;            // chunk-local s (tiles don't straddle)
        __half* pt = pTh + cid * (32 * 40);
#pragma unroll
        for (int jt = 0; jt < 4; jt++) {
            int p0 = jt * 8 + tg * 2;
            float v00 = softplus_b(pc[jt][0]);
            float v01 = softplus_b(pc[jt][1]);
            float v10 = softplus_b(pc[jt][2]);
            float v11 = softplus_b(pc[jt][3]);
            *(float2*)&g_pattn[(base + trow) * 32 + p0]     = make_float2(v00, v01);
            *(float2*)&g_pattn[(base + trow + 8) * 32 + p0] = make_float2(v10, v11);
            pt[(p0)     * 40 + sl]     = __float2half_rn(v00);
            pt[(p0 + 1) * 40 + sl]     = __float2half_rn(v01);
            pt[(p0)     * 40 + sl + 8] = __float2half_rn(v10);
            pt[(p0 + 1) * 40 + sl + 8] = __float2half_rn(v11);
        }
    }
    __syncthreads();

    // ---- phase 2: S_c[d][j] = sum_s kv[s][d] p[s][j]; warp owns d-tile wid ----
#pragma unroll
    for (int cid = 0; cid < 2; cid++) {
        float sc[4][4];
#pragma unroll
        for (int jt = 0; jt < 4; jt++)
#pragma unroll
            for (int e = 0; e < 4; e++) sc[jt][e] = 0.f;

        uint32_t av[2][4];
#pragma unroll
        for (int ks = 0; ks < 2; ks++) {
            uint32_t addr = sb + KVT + (uint32_t)(cid * 64 * 40 * 2)
                + (uint32_t)((wid * 16 + (li & 1) * 8 + lr) * 80)
                + (uint32_t)(ks * 32 + (li >> 1) * 16);
            ldsm_x4(av[ks], addr);
        }
#pragma unroll
        for (int ks = 0; ks < 2; ks++) {
            uint32_t bp[2][4];
#pragma unroll
            for (int jn = 0; jn < 2; jn++) {
                uint32_t addr = sb + PTH + (uint32_t)(cid * 32 * 40 * 2)
                    + (uint32_t)((jn * 16 + (li >> 1) * 8 + lr) * 80)
                    + (uint32_t)(ks * 32 + (li & 1) * 16);
                ldsm_x4(bp[jn], addr);
            }
#pragma unroll
            for (int jt = 0; jt < 4; jt++)
                mma16816(sc[jt], av[ks], &bp[jt >> 1][(jt & 1) * 2]);
        }
        float* o = &g_S[((size_t)bh * NSC + 2 * bx + cid) * 2048];
        const int d0 = wid * 16 + g;
#pragma unroll
        for (int jt = 0; jt < 4; jt++) {
            int j0 = jt * 8 + tg * 2;
            *(float2*)&o[d0 * 32 + j0]       = make_float2(sc[jt][0], sc[jt][1]);
            *(float2*)&o[(d0 + 8) * 32 + j0] = make_float2(sc[jt][2], sc[jt][3]);
        }
    }
}

// ------------------- exclusive prefix scan over 64 chunks ------------------
__global__ __launch_bounds__(256)
void scan_states()
{
    const int gi = blockIdx.x * 256 + threadIdx.x;
    const int bh = gi >> 11;
    const int e  = gi & 2047;
    float run = 0.f;
    float* p = &g_S[(size_t)bh * NSC * 2048 + e];
    for (int c = 0; c < NSC; c++) {
        float v = p[c * 2048];
        p[c * 2048] = run;
        run += v;
    }
}

// ------------------- fused pass1 + softmax + pass2 (R15 champion) -----------
__global__ __launch_bounds__(256, 2)
void fused_pass()
{
    const int bx = blockIdx.x, bh = blockIdx.y;
    extern __shared__ float sm[];
    float* qs  = sm;                 // 64 x 65
    float* kvs = qs  + 64 * 65;      // 64 x 64
    float* ps  = kvs + 64 * 64;      // 64 x 33
    float* ws  = ps  + 64 * 33;      // 64 x 33
    float* ss  = ws  + 64 * 33;      // 2 x 64 x 33
    float* ssT = ss  + 2 * 64 * 33;  // 2 x 32 x 65
    const size_t base = (size_t)bh * T_LEN + bx * 64;
    const int tid = threadIdx.x;

    for (int i = tid; i < 64 * 16; i += 256) {
        int s = i >> 4, d4 = i & 15;
        float4 kv4 = ((const float4*)(g_kv + (base + s) * 64))[d4];
        ((float4*)(kvs + s * 64))[d4] = kv4;
        float4 q4 = ((const float4*)(g_q + (base + s) * 64))[d4];
        float* qd = qs + s * 65 + d4 * 4;
        qd[0] = q4.x; qd[1] = q4.y; qd[2] = q4.z; qd[3] = q4.w;
    }
    for (int i = tid; i < 64 * 8; i += 256) {
        int s = i >> 3, j4 = i & 7;
        float4 p4 = ((const float4*)(g_pattn + (base + s) * 32))[j4];
        float* pd = ps + s * 33 + j4 * 4;
        pd[0] = p4.x; pd[1] = p4.y; pd[2] = p4.z; pd[3] = p4.w;
    }
    for (int i = tid; i < 2 * 64 * 8; i += 256) {
        int ci   = i >> 9;
        int idx4 = i & 511;
        int d = idx4 >> 3, j4 = idx4 & 7;
        float4 v = ((const float4*)(g_S + ((size_t)bh * NSC + 2 * bx + ci) * 2048))[idx4];
        float* sd = ss + ci * (64 * 33) + d * 33 + j4 * 4;
        sd[0] = v.x; sd[1] = v.y; sd[2] = v.z; sd[3] = v.w;
        float* st = ssT + ci * (32 * 65);
        int j0 = j4 * 4;
        st[(j0 + 0) * 65 + d] = v.x;
        st[(j0 + 1) * 65 + d] = v.y;
        st[(j0 + 2) * 65 + d] = v.z;
        st[(j0 + 3) * 65 + d] = v.w;
    }
    __syncthreads();

    const int cid = tid >> 7;
    const int lt  = (tid >> 2) & 31;
    const int sub = tid & 3;
    const int row = cid * 32 + lt;
    const int tgl = bx * 64 + row;
    const float inv = 1.0f / (float)(tgl + 1);
    const int smax = lt | 7;
    const float* ssb  = ss  + cid * (64 * 33);
    const float* ssTb = ssT + cid * (32 * 65);
    const int srow0 = cid * 32;

    // ---------------- pass 1 ----------------
    {
        const int j0  = sub * 8;
        const int dq0 = sub * 16;
        float qreg[16];
#pragma unroll
        for (int d = 0; d < 16; d++) qreg[d] = qs[row * 65 + dq0 + d];

        float r[8];
#pragma unroll
        for (int jj = 0; jj < 8; jj++) r[jj] = 0.f;

        const float* qrow = &qs[row * 65];
#pragma unroll 8
        for (int d = 0; d < 64; d++) {
            float a = qrow[d];
#pragma unroll
            for (int jj = 0; jj < 8; jj++) r[jj] += a * ssb[d * 33 + j0 + jj];
        }
        for (int s = 0; s <= smax; s++) {
            const float* kr = &kvs[(srow0 + s) * 64 + dq0];
            float a0 = 0.f, a1 = 0.f, a2 = 0.f, a3 = 0.f;
#pragma unroll
            for (int d = 0; d < 16; d += 4) {
                a0 += qreg[d]     * kr[d];
                a1 += qreg[d + 1] * kr[d + 1];
                a2 += qreg[d + 2] * kr[d + 2];
                a3 += qreg[d + 3] * kr[d + 3];
            }
            float a = (a0 + a1) + (a2 + a3);
            a += __shfl_xor_sync(0xffffffffu, a, 1);
            a += __shfl_xor_sync(0xffffffffu, a, 2);
            if (s <= lt) {
                const float* pr = &ps[(srow0 + s) * 33 + j0];
#pragma unroll
                for (int jj = 0; jj < 8; jj++) r[jj] += a * pr[jj];
            }
        }
        float mx = -1e30f;
#pragma unroll
        for (int jj = 0; jj < 8; jj++) { r[jj] *= inv; mx = fmaxf(mx, r[jj]); }
        mx = fmaxf(mx, __shfl_xor_sync(0xffffffffu, mx, 1));
        mx = fmaxf(mx, __shfl_xor_sync(0xffffffffu, mx, 2));
        float sum = 0.f;
#pragma unroll
        for (int jj = 0; jj < 8; jj++) { r[jj] = expf(r[jj] - mx); sum += r[jj]; }
        sum += __shfl_xor_sync(0xffffffffu, sum, 1);
        sum += __shfl_xor_sync(0xffffffffu, sum, 2);
        float rs = 1.0f / sum;
#pragma unroll
        for (int jj = 0; jj < 8; jj++) ws[row * 33 + j0 + jj] = r[jj] * rs;
    }
    __syncwarp();

    // ---------------- pass 2 ----------------
    {
        const int d0 = sub * 16;
        const int jw0 = sub * 8;
        float wreg[32];
#pragma unroll
        for (int j = 0; j < 32; j++) wreg[j] = ws[row * 33 + j];

        float r[16];
#pragma unroll
        for (int dd = 0; dd < 16; dd++) r[dd] = 0.f;

#pragma unroll 8
        for (int j = 0; j < 32; j++) {
            float a = wreg[j];
            const float* sr = &ssTb[j * 65 + d0];
#pragma unroll
            for (int dd = 0; dd < 16; dd++) r[dd] += a * sr[dd];
        }
        for (int s = 0; s <= smax; s++) {
            const float* pr = &ps[(srow0 + s) * 33 + jw0];
            float a0 = 0.f, a1 = 0.f;
#pragma unroll
            for (int j = 0; j < 8; j += 2) {
                a0 += wreg[jw0 + j]     * pr[j];
                a1 += wreg[jw0 + j + 1] * pr[j + 1];
            }
            float a = a0 + a1;
            a += __shfl_xor_sync(0xffffffffu, a, 1);
            a += __shfl_xor_sync(0xffffffffu, a, 2);
            if (s <= lt) {
                const float* kr = &kvs[(srow0 + s) * 64 + d0];
#pragma unroll
                for (int dd = 0; dd < 16; dd++) r[dd] += a * kr[dd];
            }
        }
        const int b = bh >> 4, hh = bh & 15;
        const size_t ob = ((size_t)tgl * 2 + b) * 1024 + hh * 64 + d0;
        __half2 h2[8];
#pragma unroll
        for (int k = 0; k < 8; k++)
            h2[k] = __half2(__float2half_rn(r[2 * k] * inv), __float2half_rn(r[2 * k + 1] * inv));
        *(uint4*)&g_ATh[ob]     = *(uint4*)&h2[0];
        *(uint4*)&g_ATh[ob + 8] = *(uint4*)&h2[4];
    }
}

// ---------------------------------------------------------------------------
extern "C" void kernel_launch(void* const* d_in, const int* in_sizes, int n_in,
                              void* d_out, int out_size)
{
    const float* query  = (const float*)d_in[0];
    const float* pquery = (const float*)d_in[1];
    const float* Wpq = (const float*)d_in[2];
    const float* bpq = (const float*)d_in[3];
    const float* Wq  = (const float*)d_in[4];
    const float* bq  = (const float*)d_in[5];
    const float* Wpc = (const float*)d_in[6];
    const float* bpc = (const float*)d_in[7];
    const float* Wc  = (const float*)d_in[8];
    const float* bc  = (const float*)d_in[9];
    const float* Wo  = (const float*)d_in[10];
    const float* bo  = (const float*)d_in[11];
    float* out = (float*)d_out;

    float *p_pq, *p_q, *p_kp, *p_kv;
    __half *p_Ah, *p_PQh, *p_W4h, *p_WOh, *p_ATh;
    cudaGetSymbolAddress((void**)&p_pq,  g_pq);
    cudaGetSymbolAddress((void**)&p_q,   g_q);
    cudaGetSymbolAddress((void**)&p_kp,  g_kp);
    cudaGetSymbolAddress((void**)&p_kv,  g_kv);
    cudaGetSymbolAddress((void**)&p_Ah,  g_Ah);
    cudaGetSymbolAddress((void**)&p_PQh, g_PQh);
    cudaGetSymbolAddress((void**)&p_W4h, g_W4h);
    cudaGetSymbolAddress((void**)&p_WOh, g_WOh);
    cudaGetSymbolAddress((void**)&p_ATh, g_ATh);

    const int GEMM_SMEM = 3 * 32768;
    const int PL_SMEM = (64 * 72 + 32 * 72 + 2 * 64 * 40 + 2 * 32 * 40) * 2;  // 29184
    const int FP_SMEM = (64 * 65 + 64 * 64 + 64 * 33 + 64 * 33 + 2 * 64 * 33 + 2 * 32 * 65) * 4;
    cudaFuncSetAttribute(gemm_mma,    cudaFuncAttributeMaxDynamicSharedMemorySize, GEMM_SMEM);
    cudaFuncSetAttribute(pattn_local, cudaFuncAttributeMaxDynamicSharedMemorySize, PL_SMEM);
    cudaFuncSetAttribute(fused_pass,  cudaFuncAttributeMaxDynamicSharedMemorySize, FP_SMEM);

    // ---- launch 0: ALL conversions ----
    CvtArgs ca;
    int acc = 0, n4;
    n4 = MROWS * E_DIM / 4;
    ca.s[0] = (const float4*)query;  ca.h[0] = (__half2*)p_Ah;  acc += n4; ca.end[0] = acc;
    n4 = 64 * E_DIM / 4;
    ca.s[1] = (const float4*)pquery; ca.h[1] = (__half2*)p_PQh; acc += n4; ca.end[1] = acc;
    n4 = NE / 4;
    ca.s[2] = (const float4*)Wq;  ca.h[2] = (__half2*)p_W4h;            acc += n4; ca.end[2] = acc;
    ca.s[3] = (const float4*)Wpc; ca.h[3] = (__half2*)(p_W4h + NE);     acc += n4; ca.end[3] = acc;
    ca.s[4] = (const float4*)Wc;  ca.h[4] = (__half2*)(p_W4h + 2 * NE); acc += n4; ca.end[4] = acc;
    ca.s[5] = (const float4*)Wpq; ca.h[5] = (__half2*)(p_W4h + 3 * NE); acc += n4; ca.end[5] = acc;
    ca.s[6] = (const float4*)Wo;  ca.h[6] = (__half2*)p_WOh;            acc += n4; ca.end[6] = acc;
    cvt_all<<<(acc + 255) / 256, 256>>>(ca);

    // ---- launch 1: q/kp/kv/pq projections (z = 0..3) ----
    gemm_mma<<<dim3(8, 32, 4), 256, GEMM_SMEM>>>(
        p_Ah, p_PQh, p_W4h,
        bq, bpc, bc, bpq,
        p_q, p_kp, p_kv, p_pq,
        SCALING, 1.0f, 1.0f, SCALING,
        MROWS, 64, 1, T_LEN, PLEN);

    // ---- launch 2: HMMA pattn + two 32-row local states ----
    pattn_local<<<dim3(T_LEN / 64, BH), 128, PL_SMEM>>>();

    // ---- launch 3: exclusive scan over 64 chunks ----
    scan_states<<<BH * 2048 / 256, 256>>>();

    // ---- launch 4: fused pass1 + softmax + pass2 ----
    fused_pass<<<dim3(T_LEN / 64, BH), 256, FP_SMEM>>>();

    // ---- launch 5: output projection -> d_out ----
    gemm_mma<<<dim3(8, 32, 1), 256, GEMM_SMEM>>>(
        p_ATh, p_ATh, p_WOh,
        bo, bo, bo, bo,
        out, out, out, out,
        1.0f, 1.0f, 1.0f, 1.0f,
        MROWS, MROWS, 0, 0, 0);
}

// round 17
// speedup vs baseline: 2.2294x; 1.0168x over previous
#include <cuda_runtime.h>
#include <cuda_fp16.h>
#include <math.h>
#include <stdint.h>

#define T_LEN  2048
#define BSZ    2
#define E_DIM  1024
#define H_NUM  16
#define D_DIM  64
#define PLEN   32
#define BH     32
#define SCH    32               // state chunk
#define NSC    (T_LEN/SCH)      // 64
#define SCALING 0.125f
#define BETA    0.6931471805599453f

#define MROWS  (T_LEN*BSZ)      // 4096
#define NE     (E_DIM*E_DIM)

// ------------------------- scratch -----------------------------------------
__device__ float g_pq   [BH*PLEN*D_DIM];
__device__ float g_q    [BH*T_LEN*D_DIM];
__device__ float g_kp   [BH*T_LEN*D_DIM];
__device__ float g_kv   [BH*T_LEN*D_DIM];
__device__ float g_pattn[BH*T_LEN*PLEN];
__device__ float g_S    [BH*NSC*D_DIM*PLEN];

__device__ __half g_Ah  [MROWS*E_DIM];
__device__ __half g_PQh [64*E_DIM];
__device__ __half g_W4h [4*NE];          // Wq, Wpc, Wc, Wpq
__device__ __half g_WOh [NE];
__device__ __half g_ATh [MROWS*E_DIM];

// ------------------------- helpers -----------------------------------------
__device__ __forceinline__ uint32_t smem_u32(const void* p) {
    uint32_t a;
    asm("{ .reg .u64 t; cvta.to.shared.u64 t, %1; cvt.u32.u64 %0, t; }"
        : "=r"(a) : "l"(p));
    return a;
}
__device__ __forceinline__ uint32_t sw128(uint32_t off) {
    return off ^ ((off >> 3) & 0x70);
}
__device__ __forceinline__ void ldsm_x4(uint32_t* r, uint32_t addr) {
    asm volatile("ldmatrix.sync.aligned.m8n8.x4.shared.b16 {%0,%1,%2,%3}, [%4];"
                 : "=r"(r[0]), "=r"(r[1]), "=r"(r[2]), "=r"(r[3]) : "r"(addr));
}
__device__ __forceinline__ void mma16816(float* c, const uint32_t* a, const uint32_t* b) {
    asm volatile("mma.sync.aligned.m16n8k16.row.col.f32.f16.f16.f32 "
                 "{%0,%1,%2,%3}, {%4,%5,%6,%7}, {%8,%9}, {%0,%1,%2,%3};"
                 : "+f"(c[0]), "+f"(c[1]), "+f"(c[2]), "+f"(c[3])
                 : "r"(a[0]), "r"(a[1]), "r"(a[2]), "r"(a[3]), "r"(b[0]), "r"(b[1]));
}
__device__ __forceinline__ void cp16(uint32_t dst, const void* src, int sz) {
    asm volatile("cp.async.cg.shared.global [%0], [%1], 16, %2;"
                 :: "r"(dst), "l"(src), "r"(sz));
}
__device__ __forceinline__ void cp_commit() {
    asm volatile("cp.async.commit_group;" ::: "memory");
}
__device__ __forceinline__ void cp_wait1() {
    asm volatile("cp.async.wait_group 1;" ::: "memory");
}
__device__ __forceinline__ void cp_wait0() {
    asm volatile("cp.async.wait_group 0;" ::: "memory");
}
__device__ __forceinline__ float softplus_b(float accv) {
    float zz = BETA * accv;
    return (fmaxf(zz, 0.f) + log1pf(expf(-fabsf(zz)))) * (1.0f / BETA);
}

// ------------------------- merged fp32 -> fp16 converter -------------------
#define NCVT 7
struct CvtArgs {
    const float4* s[NCVT];
    __half2*      h[NCVT];
    int           end[NCVT];
};

__global__ __launch_bounds__(256)
void cvt_all(CvtArgs A)
{
    int gi = blockIdx.x * 256 + threadIdx.x;
    int seg = 0;
    while (seg < NCVT && gi >= A.end[seg]) seg++;
    if (seg >= NCVT) return;
    int i = gi - (seg ? A.end[seg - 1] : 0);

    float4 v = A.s[seg][i];
    A.h[seg][2 * i]     = __half2(__float2half_rn(v.x), __float2half_rn(v.y));
    A.h[seg][2 * i + 1] = __half2(__float2half_rn(v.z), __float2half_rn(v.w));
}

// ------------------------- pipelined fp16 GEMM (R10 form) -------------------
__device__ __forceinline__ void g_load_stage(
    uint32_t sb, int slot,
    const __half* Ah, const __half* Bh,
    int bm, int bn, int kb, int M, int tid)
{
    const uint32_t abase = sb + slot * 32768;
    const uint32_t bbase = abase + 16384;
    const int c  = tid & 7;
    const int r0 = tid >> 3;
    const int kc = kb + c * 8;
#pragma unroll
    for (int ii = 0; ii < 4; ii++) {
        int r = r0 + ii * 32;
        uint32_t so = sw128((uint32_t)(r * 128 + c * 16));
        int m = bm + r;
        int mc = (m < M) ? m : (M - 1);
        cp16(abase + so, Ah + (size_t)mc * E_DIM + kc, (m < M) ? 16 : 0);
        cp16(bbase + so, Bh + (size_t)(bn + r) * E_DIM + kc, 16);
    }
}

__global__ __launch_bounds__(256, 2)
void gemm_mma(const __half* __restrict__ A0, const __half* __restrict__ A3,
              const __half* __restrict__ W,
              const float* b0, const float* b1, const float* b2, const float* b3,
              float* o0, float* o1, float* o2, float* o3,
              float s0, float s1, float s2, float s3,
              int M0, int M3, int mode, int Trows0, int Trows3)
{
    extern __shared__ char smem[];
    const uint32_t sb = smem_u32(smem);

    const int tid = threadIdx.x, wid = tid >> 5, lane = tid & 31;
    const int bm = blockIdx.y * 128, bn = blockIdx.x * 128;
    const int z = blockIdx.z;
    const int M     = (z == 3) ? M3 : M0;
    const int Trows = (z == 3) ? Trows3 : Trows0;
    if (bm >= M) return;
    const __half* Ah = (z == 3) ? A3 : A0;
    const __half* wh = W + (size_t)z * NE;
    const float* bias = (z == 0) ? b0 : ((z == 1) ? b1 : ((z == 2) ? b2 : b3));
    float* out        = (z == 0) ? o0 : ((z == 1) ? o1 : ((z == 2) ? o2 : o3));
    const float scale = (z == 0) ? s0 : ((z == 1) ? s1 : ((z == 2) ? s2 : s3));

    const int warpM = (wid >> 2) * 64;
    const int warpN = (wid & 3) * 32;
    const int li = lane >> 3, lr = lane & 7;

    float acc[4][4][4];
#pragma unroll
    for (int i = 0; i < 4; i++)
#pragma unroll
        for (int j = 0; j < 4; j++)
#pragma unroll
            for (int k = 0; k < 4; k++) acc[i][j][k] = 0.f;

    const int NK = E_DIM / 64;
    g_load_stage(sb, 0, Ah, wh, bm, bn, 0, M, tid);
    cp_commit();
    g_load_stage(sb, 1, Ah, wh, bm, bn, 64, M, tid);
    cp_commit();

    int slot = 0, next = 2;
    for (int ks = 0; ks < NK; ks++) {
        if (ks + 1 < NK) cp_wait1(); else cp_wait0();
        __syncthreads();
        if (ks + 2 < NK) {
            g_load_stage(sb, next, Ah, wh, bm, bn, (ks + 2) * 64, M, tid);
            cp_commit();
            if (++next == 3) next = 0;
        }

        const uint32_t abase = sb + slot * 32768;
        const uint32_t bbase = abase + 16384;
        if (++slot == 3) slot = 0;
#pragma unroll
        for (int kk = 0; kk < 4; kk++) {
            uint32_t bfr[2][4];
            const uint32_t kb2 = (uint32_t)(kk * 32 + (li & 1) * 16);
#pragma unroll
            for (int jn = 0; jn < 2; jn++) {
                uint32_t off = (uint32_t)((warpN + jn * 16 + (li >> 1) * 8 + lr) * 128) + kb2;
                ldsm_x4(bfr[jn], bbase + sw128(off));
            }
            const uint32_t ka = (uint32_t)(kk * 32 + (li >> 1) * 16);
#pragma unroll
            for (int i = 0; i < 4; i++) {
                uint32_t ah[4];
                uint32_t off = (uint32_t)((warpM + i * 16 + (li & 1) * 8 + lr) * 128) + ka;
                ldsm_x4(ah, abase + sw128(off));
#pragma unroll
                for (int j = 0; j < 4; j++)
                    mma16816(acc[i][j], ah, &bfr[j >> 1][(j & 1) * 2]);
            }
        }
    }

    const int g = lane >> 2, tg = lane & 3;
#pragma unroll
    for (int i = 0; i < 4; i++) {
#pragma unroll
        for (int j = 0; j < 4; j++) {
            int n0 = bn + warpN + j * 8 + tg * 2;
            float bx = bias[n0], by = bias[n0 + 1];
#pragma unroll
            for (int half = 0; half < 2; half++) {
                int m = bm + warpM + i * 16 + g + half * 8;
                if (m >= M) continue;
                float2 v;
                v.x = (acc[i][j][half * 2 + 0] + bx) * scale;
                v.y = (acc[i][j][half * 2 + 1] + by) * scale;
                if (mode == 0) {
                    *(float2*)&out[(size_t)m * E_DIM + n0] = v;
                } else {
                    int t = m >> 1, b = m & 1;
                    int h = n0 >> 6, d = n0 & 63;
                    *(float2*)&out[(size_t)((b * 16 + h) * Trows + t) * 64 + d] = v;
                }
            }
        }
    }
}

// ------------- HMMA pattn (softplus) + TWO 32-row local states --------------
__global__ __launch_bounds__(128, 4)
void pattn_local()
{
    const int bx = blockIdx.x, bh = blockIdx.y;
    extern __shared__ char smc[];
    __half* kph  = (__half*)smc;            // 64 x 72
    __half* pqh  = kph + 64 * 72;           // 32 x 72
    __half* kvTh = pqh + 32 * 72;           // 2 x 64 x 40  [cid][d][s]
    __half* pTh  = kvTh + 2 * 64 * 40;      // 2 x 32 x 40  [cid][p][s]
    const size_t base = (size_t)bh * T_LEN + bx * 64;
    const int tid = threadIdx.x;
    const int wid = tid >> 5, lane = tid & 31;
    const int li = lane >> 3, lr = lane & 7;
    const int g = lane >> 2, tg = lane & 3;

    for (int i = tid; i < 64 * 16; i += 128) {
        int s = i >> 4, d4 = i & 15;
        float4 kp4 = ((const float4*)(g_kp + (base + s) * 64))[d4];
        __half* kd = kph + s * 72 + d4 * 4;
        kd[0] = __float2half_rn(kp4.x); kd[1] = __float2half_rn(kp4.y);
        kd[2] = __float2half_rn(kp4.z); kd[3] = __float2half_rn(kp4.w);
        float4 kv4 = ((const float4*)(g_kv + (base + s) * 64))[d4];
        int cid = s >> 5, sl = s & 31;
        __half* kt = kvTh + cid * (64 * 40) + (d4 * 4) * 40 + sl;
        kt[0]   = __float2half_rn(kv4.x);
        kt[40]  = __float2half_rn(kv4.y);
        kt[80]  = __float2half_rn(kv4.z);
        kt[120] = __float2half_rn(kv4.w);
    }
    for (int i = tid; i < 32 * 16; i += 128) {
        int p = i >> 4, d4 = i & 15;
        float4 v = ((const float4*)(g_pq + (size_t)bh * PLEN * D_DIM + p * 64))[d4];
        __half* pd = pqh + p * 72 + d4 * 4;
        pd[0] = __float2half_rn(v.x); pd[1] = __float2half_rn(v.y);
        pd[2] = __float2half_rn(v.z); pd[3] = __float2half_rn(v.w);
    }
    __syncthreads();

    const uint32_t sb  = smem_u32(smc);
    const uint32_t KPH = 0;
    const uint32_t PQH = 64 * 72 * 2;
    const uint32_t KVT = PQH + 32 * 72 * 2;
    const uint32_t PTH = KVT + 2 * 64 * 40 * 2;

    // ---- phase 1: pattn rows wid*16 .. wid*16+16 ----
    {
        float pc[4][4];
#pragma unroll
        for (int jt = 0; jt < 4; jt++)
#pragma unroll
            for (int e = 0; e < 4; e++) pc[jt][e] = 0.f;

        uint32_t aq[4][4];
#pragma unroll
        for (int kk = 0; kk < 4; kk++) {
            uint32_t addr = sb + KPH
                + (uint32_t)((wid * 16 + (li & 1) * 8 + lr) * 144)
                + (uint32_t)(kk * 32 + (li >> 1) * 16);
            ldsm_x4(aq[kk], addr);
        }
#pragma unroll
        for (int kk = 0; kk < 4; kk++) {
            uint32_t bq[2][4];
#pragma unroll
            for (int jn = 0; jn < 2; jn++) {
                uint32_t addr = sb + PQH
                    + (uint32_t)((jn * 16 + (li >> 1) * 8 + lr) * 144)
                    + (uint32_t)(kk * 32 + (li & 1) * 16);
                ldsm_x4(bq[jn], addr);
            }
#pragma unroll
            for (int jt = 0; jt < 4; jt++)
                mma16816(pc[jt], aq[kk], &bq[jt >> 1][(jt & 1) * 2]);
        }

        const int trow = wid * 16 + g;
        const int cid  = wid >> 1;
        const int sl   = trow & 31;
        __half* pt = pTh + cid * (32 * 40);
#pragma unroll
        for (int jt = 0; jt < 4; jt++) {
            int p0 = jt * 8 + tg * 2;
            float v00 = softplus_b(pc[jt][0]);
            float v01 = softplus_b(pc[jt][1]);
            float v10 = softplus_b(pc[jt][2]);
            float v11 = softplus_b(pc[jt][3]);
            *(float2*)&g_pattn[(base + trow) * 32 + p0]     = make_float2(v00, v01);
            *(float2*)&g_pattn[(base + trow + 8) * 32 + p0] = make_float2(v10, v11);
            pt[(p0)     * 40 + sl]     = __float2half_rn(v00);
            pt[(p0 + 1) * 40 + sl]     = __float2half_rn(v01);
            pt[(p0)     * 40 + sl + 8] = __float2half_rn(v10);
            pt[(p0 + 1) * 40 + sl + 8] = __float2half_rn(v11);
        }
    }
    __syncthreads();

    // ---- phase 2: S_c[d][j] = sum_s kv[s][d] p[s][j] ----
#pragma unroll
    for (int cid = 0; cid < 2; cid++) {
        float sc[4][4];
#pragma unroll
        for (int jt = 0; jt < 4; jt++)
#pragma unroll
            for (int e = 0; e < 4; e++) sc[jt][e] = 0.f;

        uint32_t av[2][4];
#pragma unroll
        for (int ks = 0; ks < 2; ks++) {
            uint32_t addr = sb + KVT + (uint32_t)(cid * 64 * 40 * 2)
                + (uint32_t)((wid * 16 + (li & 1) * 8 + lr) * 80)
                + (uint32_t)(ks * 32 + (li >> 1) * 16);
            ldsm_x4(av[ks], addr);
        }
#pragma unroll
        for (int ks = 0; ks < 2; ks++) {
            uint32_t bp[2][4];
#pragma unroll
            for (int jn = 0; jn < 2; jn++) {
                uint32_t addr = sb + PTH + (uint32_t)(cid * 32 * 40 * 2)
                    + (uint32_t)((jn * 16 + (li >> 1) * 8 + lr) * 80)
                    + (uint32_t)(ks * 32 + (li & 1) * 16);
                ldsm_x4(bp[jn], addr);
            }
#pragma unroll
            for (int jt = 0; jt < 4; jt++)
                mma16816(sc[jt], av[ks], &bp[jt >> 1][(jt & 1) * 2]);
        }
        float* o = &g_S[((size_t)bh * NSC + 2 * bx + cid) * 2048];
        const int d0 = wid * 16 + g;
#pragma unroll
        for (int jt = 0; jt < 4; jt++) {
            int j0 = jt * 8 + tg * 2;
            *(float2*)&o[d0 * 32 + j0]       = make_float2(sc[jt][0], sc[jt][1]);
            *(float2*)&o[(d0 + 8) * 32 + j0] = make_float2(sc[jt][2], sc[jt][3]);
        }
    }
}

// ------------------- exclusive prefix scan over 64 chunks (unroll 4) -------
__global__ __launch_bounds__(256)
void scan_states()
{
    const int gi = blockIdx.x * 256 + threadIdx.x;
    const int bh = gi >> 11;
    const int e  = gi & 2047;
    float run = 0.f;
    float* p = &g_S[(size_t)bh * NSC * 2048 + e];
    for (int c = 0; c < NSC; c += 4) {
        float v0 = p[(c + 0) * 2048];
        float v1 = p[(c + 1) * 2048];
        float v2 = p[(c + 2) * 2048];
        float v3 = p[(c + 3) * 2048];
        p[(c + 0) * 2048] = run; run += v0;
        p[(c + 1) * 2048] = run; run += v1;
        p[(c + 2) * 2048] = run; run += v2;
        p[(c + 3) * 2048] = run; run += v3;
    }
}

// ------------------- fused pass1 + softmax + pass2 (float4 smem) ------------
// strides: qs 68, kvs 64, ps 36, ws 36, ss 36, ssT 68 (all 16B-aligned rows).
__global__ __launch_bounds__(256, 2)
void fused_pass()
{
    const int bx = blockIdx.x, bh = blockIdx.y;
    extern __shared__ float sm[];
    float* qs  = sm;                 // 64 x 68
    float* kvs = qs  + 64 * 68;      // 64 x 64
    float* ps  = kvs + 64 * 64;      // 64 x 36
    float* ws  = ps  + 64 * 36;      // 64 x 36
    float* ss  = ws  + 64 * 36;      // 2 x 64 x 36
    float* ssT = ss  + 2 * 64 * 36;  // 2 x 32 x 68
    const size_t base = (size_t)bh * T_LEN + bx * 64;
    const int tid = threadIdx.x;

    for (int i = tid; i < 64 * 16; i += 256) {
        int s = i >> 4, d4 = i & 15;
        float4 kv4 = ((const float4*)(g_kv + (base + s) * 64))[d4];
        ((float4*)(kvs + s * 64))[d4] = kv4;
        float4 q4 = ((const float4*)(g_q + (base + s) * 64))[d4];
        ((float4*)(qs + s * 68))[d4] = q4;
    }
    for (int i = tid; i < 64 * 8; i += 256) {
        int s = i >> 3, j4 = i & 7;
        float4 p4 = ((const float4*)(g_pattn + (base + s) * 32))[j4];
        ((float4*)(ps + s * 36))[j4] = p4;
    }
    for (int i = tid; i < 2 * 64 * 8; i += 256) {
        int ci   = i >> 9;
        int idx4 = i & 511;
        int d = idx4 >> 3, j4 = idx4 & 7;
        float4 v = ((const float4*)(g_S + ((size_t)bh * NSC + 2 * bx + ci) * 2048))[idx4];
        ((float4*)(ss + ci * (64 * 36) + d * 36))[j4] = v;
        float* st = ssT + ci * (32 * 68);
        int j0 = j4 * 4;
        st[(j0 + 0) * 68 + d] = v.x;
        st[(j0 + 1) * 68 + d] = v.y;
        st[(j0 + 2) * 68 + d] = v.z;
        st[(j0 + 3) * 68 + d] = v.w;
    }
    __syncthreads();

    const int cid = tid >> 7;
    const int lt  = (tid >> 2) & 31;
    const int sub = tid & 3;
    const int row = cid * 32 + lt;
    const int tgl = bx * 64 + row;
    const float inv = 1.0f / (float)(tgl + 1);
    const int smax = lt | 7;
    const float* ssb  = ss  + cid * (64 * 36);
    const float* ssTb = ssT + cid * (32 * 68);
    const int srow0 = cid * 32;

    // ---------------- pass 1 ----------------
    {
        const int j0  = sub * 8;
        const int dq0 = sub * 16;
        float4 q4[4];
        const float4* qsp = (const float4*)&qs[row * 68 + dq0];
#pragma unroll
        for (int k = 0; k < 4; k++) q4[k] = qsp[k];

        float r[8];
#pragma unroll
        for (int jj = 0; jj < 8; jj++) r[jj] = 0.f;

        // inter-chunk: q[t] @ S_prefix (float4 reads, broadcast across rows)
        const float* qrow = &qs[row * 68];
#pragma unroll 8
        for (int d = 0; d < 64; d++) {
            float a = qrow[d];
            const float4* sr = (const float4*)&ssb[d * 36 + j0];
            float4 sa = sr[0], sb2 = sr[1];
            r[0] += a * sa.x;  r[1] += a * sa.y;  r[2] += a * sa.z;  r[3] += a * sa.w;
            r[4] += a * sb2.x; r[5] += a * sb2.y; r[6] += a * sb2.z; r[7] += a * sb2.w;
        }
        // intra-chunk causal
        for (int s = 0; s <= smax; s++) {
            const float4* kr = (const float4*)&kvs[(srow0 + s) * 64 + dq0];
            float a0 = 0.f, a1 = 0.f, a2 = 0.f, a3 = 0.f;
#pragma unroll
            for (int k = 0; k < 4; k++) {
                float4 k4 = kr[k];
                a0 += q4[k].x * k4.x;
                a1 += q4[k].y * k4.y;
                a2 += q4[k].z * k4.z;
                a3 += q4[k].w * k4.w;
            }
            float a = (a0 + a1) + (a2 + a3);
            a += __shfl_xor_sync(0xffffffffu, a, 1);
            a += __shfl_xor_sync(0xffffffffu, a, 2);
            if (s <= lt) {
                const float4* pr = (const float4*)&ps[(srow0 + s) * 36 + j0];
                float4 pa = pr[0], pb = pr[1];
                r[0] += a * pa.x; r[1] += a * pa.y; r[2] += a * pa.z; r[3] += a * pa.w;
                r[4] += a * pb.x; r[5] += a * pb.y; r[6] += a * pb.z; r[7] += a * pb.w;
            }
        }
        float mx = -1e30f;
#pragma unroll
        for (int jj = 0; jj < 8; jj++) { r[jj] *= inv; mx = fmaxf(mx, r[jj]); }
        mx = fmaxf(mx, __shfl_xor_sync(0xffffffffu, mx, 1));
        mx = fmaxf(mx, __shfl_xor_sync(0xffffffffu, mx, 2));
        float sum = 0.f;
#pragma unroll
        for (int jj = 0; jj < 8; jj++) { r[jj] = expf(r[jj] - mx); sum += r[jj]; }
        sum += __shfl_xor_sync(0xffffffffu, sum, 1);
        sum += __shfl_xor_sync(0xffffffffu, sum, 2);
        float rs = 1.0f / sum;
        float4* wp = (float4*)&ws[row * 36 + j0];
        wp[0] = make_float4(r[0] * rs, r[1] * rs, r[2] * rs, r[3] * rs);
        wp[1] = make_float4(r[4] * rs, r[5] * rs, r[6] * rs, r[7] * rs);
    }
    __syncwarp();

    // ---------------- pass 2 ----------------
    {
        const int d0 = sub * 16;
        float4 w4[8];
        const float4* wsp = (const float4*)&ws[row * 36];
#pragma unroll
        for (int k = 0; k < 8; k++) w4[k] = wsp[k];
        const float* wreg = (const float*)w4;

        float r[16];
#pragma unroll
        for (int dd = 0; dd < 16; dd++) r[dd] = 0.f;

        // inter-chunk: w[t] @ S^T_prefix (float4 reads)
#pragma unroll 8
        for (int j = 0; j < 32; j++) {
            float a = wreg[j];
            const float4* sr = (const float4*)&ssTb[j * 68 + d0];
#pragma unroll
            for (int k = 0; k < 4; k++) {
                float4 s4 = sr[k];
                r[4 * k + 0] += a * s4.x;
                r[4 * k + 1] += a * s4.y;
                r[4 * k + 2] += a * s4.z;
                r[4 * k + 3] += a * s4.w;
            }
        }
        // intra-chunk causal
        const int jw0 = sub * 8;
        const float4* wq = &w4[sub * 2];
        for (int s = 0; s <= smax; s++) {
            const float4* pr = (const float4*)&ps[(srow0 + s) * 36 + jw0];
            float4 pa = pr[0], pb = pr[1];
            float a0 = wq[0].x * pa.x + wq[0].y * pa.y + wq[0].z * pa.z + wq[0].w * pa.w;
            float a1 = wq[1].x * pb.x + wq[1].y * pb.y + wq[1].z * pb.z + wq[1].w * pb.w;
            float a = a0 + a1;
            a += __shfl_xor_sync(0xffffffffu, a, 1);
            a += __shfl_xor_sync(0xffffffffu, a, 2);
            if (s <= lt) {
                const float4* kr = (const float4*)&kvs[(srow0 + s) * 64 + d0];
#pragma unroll
                for (int k = 0; k < 4; k++) {
                    float4 k4 = kr[k];
                    r[4 * k + 0] += a * k4.x;
                    r[4 * k + 1] += a * k4.y;
                    r[4 * k + 2] += a * k4.z;
                    r[4 * k + 3] += a * k4.w;
                }
            }
        }
        const int b = bh >> 4, hh = bh & 15;
        const size_t ob = ((size_t)tgl * 2 + b) * 1024 + hh * 64 + d0;
        __half2 h2[8];
#pragma unroll
        for (int k = 0; k < 8; k++)
            h2[k] = __half2(__float2half_rn(r[2 * k] * inv), __float2half_rn(r[2 * k + 1] * inv));
        *(uint4*)&g_ATh[ob]     = *(uint4*)&h2[0];
        *(uint4*)&g_ATh[ob + 8] = *(uint4*)&h2[4];
    }
}

// ---------------------------------------------------------------------------
extern "C" void kernel_launch(void* const* d_in, const int* in_sizes, int n_in,
                              void* d_out, int out_size)
{
    const float* query  = (const float*)d_in[0];
    const float* pquery = (const float*)d_in[1];
    const float* Wpq = (const float*)d_in[2];
    const float* bpq = (const float*)d_in[3];
    const float* Wq  = (const float*)d_in[4];
    const float* bq  = (const float*)d_in[5];
    const float* Wpc = (const float*)d_in[6];
    const float* bpc = (const float*)d_in[7];
    const float* Wc  = (const float*)d_in[8];
    const float* bc  = (const float*)d_in[9];
    const float* Wo  = (const float*)d_in[10];
    const float* bo  = (const float*)d_in[11];
    float* out = (float*)d_out;

    float *p_pq, *p_q, *p_kp, *p_kv;
    __half *p_Ah, *p_PQh, *p_W4h, *p_WOh, *p_ATh;
    cudaGetSymbolAddress((void**)&p_pq,  g_pq);
    cudaGetSymbolAddress((void**)&p_q,   g_q);
    cudaGetSymbolAddress((void**)&p_kp,  g_kp);
    cudaGetSymbolAddress((void**)&p_kv,  g_kv);
    cudaGetSymbolAddress((void**)&p_Ah,  g_Ah);
    cudaGetSymbolAddress((void**)&p_PQh, g_PQh);
    cudaGetSymbolAddress((void**)&p_W4h, g_W4h);
    cudaGetSymbolAddress((void**)&p_WOh, g_WOh);
    cudaGetSymbolAddress((void**)&p_ATh, g_ATh);

    const int GEMM_SMEM = 3 * 32768;
    const int PL_SMEM = (64 * 72 + 32 * 72 + 2 * 64 * 40 + 2 * 32 * 40) * 2;  // 29184
    const int FP_SMEM = (64 * 68 + 64 * 64 + 64 * 36 + 64 * 36 + 2 * 64 * 36 + 2 * 32 * 68) * 4; // 88064
    cudaFuncSetAttribute(gemm_mma,    cudaFuncAttributeMaxDynamicSharedMemorySize, GEMM_SMEM);
    cudaFuncSetAttribute(pattn_local, cudaFuncAttributeMaxDynamicSharedMemorySize, PL_SMEM);
    cudaFuncSetAttribute(fused_pass,  cudaFuncAttributeMaxDynamicSharedMemorySize, FP_SMEM);

    // ---- launch 0: ALL conversions ----
    CvtArgs ca;
    int acc = 0, n4;
    n4 = MROWS * E_DIM / 4;
    ca.s[0] = (const float4*)query;  ca.h[0] = (__half2*)p_Ah;  acc += n4; ca.end[0] = acc;
    n4 = 64 * E_DIM / 4;
    ca.s[1] = (const float4*)pquery; ca.h[1] = (__half2*)p_PQh; acc += n4; ca.end[1] = acc;
    n4 = NE / 4;
    ca.s[2] = (const float4*)Wq;  ca.h[2] = (__half2*)p_W4h;            acc += n4; ca.end[2] = acc;
    ca.s[3] = (const float4*)Wpc; ca.h[3] = (__half2*)(p_W4h + NE);     acc += n4; ca.end[3] = acc;
    ca.s[4] = (const float4*)Wc;  ca.h[4] = (__half2*)(p_W4h + 2 * NE); acc += n4; ca.end[4] = acc;
    ca.s[5] = (const float4*)Wpq; ca.h[5] = (__half2*)(p_W4h + 3 * NE); acc += n4; ca.end[5] = acc;
    ca.s[6] = (const float4*)Wo;  ca.h[6] = (__half2*)p_WOh;            acc += n4; ca.end[6] = acc;
    cvt_all<<<(acc + 255) / 256, 256>>>(ca);

    // ---- launch 1: q/kp/kv/pq projections (z = 0..3) ----
    gemm_mma<<<dim3(8, 32, 4), 256, GEMM_SMEM>>>(
        p_Ah, p_PQh, p_W4h,
        bq, bpc, bc, bpq,
        p_q, p_kp, p_kv, p_pq,
        SCALING, 1.0f, 1.0f, SCALING,
        MROWS, 64, 1, T_LEN, PLEN);

    // ---- launch 2: HMMA pattn + two 32-row local states ----
    pattn_local<<<dim3(T_LEN / 64, BH), 128, PL_SMEM>>>();

    // ---- launch 3: exclusive scan over 64 chunks ----
    scan_states<<<BH * 2048 / 256, 256>>>();

    // ---- launch 4: fused pass1 + softmax + pass2 ----
    fused_pass<<<dim3(T_LEN / 64, BH), 256, FP_SMEM>>>();

    // ---- launch 5: output projection -> d_out ----
    gemm_mma<<<dim3(8, 32, 1), 256, GEMM_SMEM>>>(
        p_ATh, p_ATh, p_WOh,
        bo, bo, bo, bo,
        out, out, out, out,
        1.0f, 1.0f, 1.0f, 1.0f,
        MROWS, MROWS, 0, 0, 0);
}